// round 11
// baseline (speedup 1.0000x reference)
#include <cuda_runtime.h>
#include <cuda_fp16.h>
#include <cstdint>
#include <math.h>

// Problem constants
#define BB   512
#define DD   1024
#define HH   4096
#define TT   21
#define TAUV 20
#define KTOP 100
#define KTOT (TT * HH)        // 86016
#define BK   64
#define SST  72               // smem k-stride in halves (144 B = 9*16B)
#define TEN_BYTES (128 * SST * 2)     // 18432 B per tensor per stage
#define STG  (2 * TEN_BYTES)          // A|B per stage = 36864
#define NST  4
#define SMEM_MMA (NST * STG)          // 147456

// ---------------------------------------------------------------------------
// Static device scratch (no allocations allowed)
// ---------------------------------------------------------------------------
__device__ __half g_X16[(size_t)TT * BB * DD];   // X fp16 [t][b][d]
__device__ float  g_X20[(size_t)BB * DD];        // X[:,:,20] fp32 compact
__device__ __half g_Fe16[(size_t)HH * DD];       // F_enc^T fp16 [h][d]
__device__ __half g_Fd16[(size_t)DD * HH];       // F_dec^T fp16 [d][h]
__device__ __half g_A16[(size_t)BB * KTOT];      // Zp fp16 [b][layer*H+h']
__device__ __half g_B16[(size_t)HH * KTOT];      // Bs/trilM fp16 [h][layer*H+d]
__device__ float g_Zlast[(size_t)BB * HH];       // fp32 Z_last (from k_zp t=20)
__device__ float g_Zt   [(size_t)BB * HH];
// 0=sum|Bs| 1=sum|trilM| 2=sseX 3=sseZ 4=sumAbsE 5=sum|Zt|
__device__ double g_acc[8];

// ---------------------------------------------------------------------------
// PTX helpers (base-target only: cp.async / ldmatrix / mma.sync)
// ---------------------------------------------------------------------------
__device__ __forceinline__ uint32_t smem_u32(const void* p) {
    uint32_t a;
    asm("{ .reg .u64 t; cvta.to.shared.u64 t, %1; cvt.u32.u64 %0, t; }"
        : "=r"(a) : "l"(p));
    return a;
}
__device__ __forceinline__ void cp_async16(uint32_t saddr, const void* gaddr) {
    asm volatile("cp.async.cg.shared.global [%0], [%1], 16;"
                 :: "r"(saddr), "l"(gaddr) : "memory");
}
__device__ __forceinline__ void cp_commit() {
    asm volatile("cp.async.commit_group;" ::: "memory");
}
__device__ __forceinline__ void cp_wait2() {
    asm volatile("cp.async.wait_group 2;" ::: "memory");
}
__device__ __forceinline__ void cp_wait1() {
    asm volatile("cp.async.wait_group 1;" ::: "memory");
}
__device__ __forceinline__ void cp_wait0() {
    asm volatile("cp.async.wait_group 0;" ::: "memory");
}
__device__ __forceinline__ void ldsm_x4(uint32_t* r, uint32_t addr) {
    asm volatile("ldmatrix.sync.aligned.m8n8.x4.shared.b16 {%0,%1,%2,%3}, [%4];"
                 : "=r"(r[0]), "=r"(r[1]), "=r"(r[2]), "=r"(r[3]) : "r"(addr));
}
__device__ __forceinline__ void mma_f16(float* c, const uint32_t* a, const uint32_t* b) {
    asm volatile(
        "mma.sync.aligned.m16n8k16.row.col.f32.f16.f16.f32 "
        "{%0,%1,%2,%3}, {%4,%5,%6,%7}, {%8,%9}, {%0,%1,%2,%3};"
        : "+f"(c[0]), "+f"(c[1]), "+f"(c[2]), "+f"(c[3])
        : "r"(a[0]), "r"(a[1]), "r"(a[2]), "r"(a[3]), "r"(b[0]), "r"(b[1]));
}

// ---------------------------------------------------------------------------
// fp16 mainloop: acc += A*B over K = KT (per-row strides strA/strB).
// CTA 128x128, 8 warps (2m x 4n), warp tile 64x32, BK=64, 4-stage cp.async,
// single __syncthreads per chunk (stage reuse is post-barrier safe).
// ---------------------------------------------------------------------------
template <int KT>
__device__ __forceinline__ void mma_mainloop_f16(
    const __half* __restrict__ A, size_t strA,
    const __half* __restrict__ B, size_t strB,
    char* smem, float acc[4][4][4])
{
    const int tid  = threadIdx.x;
    const int lane = tid & 31, warp = tid >> 5;
    const int wm = warp & 1, wn = warp >> 1;
    const uint32_t sbase = smem_u32(smem);

    const int lrow = tid >> 1;
    const int lkh  = (tid & 1) * 32;          // half offset within the 64-k chunk
    const size_t growA = (size_t)lrow * strA + lkh;
    const size_t growB = (size_t)lrow * strB + lkh;
    constexpr int NKT = KT / BK;

    auto issue = [&](int kt) {
        const int s = kt & (NST - 1);
        const __half* ga = A + growA + (size_t)kt * BK;
        const __half* gb = B + growB + (size_t)kt * BK;
        const uint32_t so = sbase + s * STG + (lrow * SST + lkh) * 2;
        cp_async16(so,      ga);
        cp_async16(so + 16, ga + 8);
        cp_async16(so + 32, ga + 16);
        cp_async16(so + 48, ga + 24);
        const uint32_t sb = so + TEN_BYTES;
        cp_async16(sb,      gb);
        cp_async16(sb + 16, gb + 8);
        cp_async16(sb + 32, gb + 16);
        cp_async16(sb + 48, gb + 24);
        cp_commit();
    };

    issue(0); issue(1); issue(2);

    const int arow = lane & 15, akc = (lane >> 4) * 8;
    const int brow = lane & 15, bkc = (lane >> 4) * 8;

    for (int kt = 0; kt < NKT; kt++) {
        if (kt + 2 < NKT)      cp_wait2();
        else if (kt + 1 < NKT) cp_wait1();
        else                   cp_wait0();
        __syncthreads();
        if (kt + 3 < NKT) issue(kt + 3);   // overwrites stage (kt-1)&3: safe post-barrier

        const uint32_t tb = sbase + (kt & (NST - 1)) * STG;
#pragma unroll
        for (int kk = 0; kk < 4; kk++) {
            uint32_t a[4][4], bh[4][2];
#pragma unroll
            for (int mi = 0; mi < 4; mi++)
                ldsm_x4(a[mi], tb + ((wm * 64 + mi * 16 + arow) * SST + kk * 16 + akc) * 2);
#pragma unroll
            for (int p = 0; p < 2; p++) {
                uint32_t r[4];
                ldsm_x4(r, tb + TEN_BYTES +
                        ((wn * 32 + p * 16 + brow) * SST + kk * 16 + bkc) * 2);
                bh[2 * p][0] = r[0];     bh[2 * p][1] = r[2];
                bh[2 * p + 1][0] = r[1]; bh[2 * p + 1][1] = r[3];
            }
#pragma unroll
            for (int mi = 0; mi < 4; mi++)
#pragma unroll
                for (int ni = 0; ni < 4; ni++)
                    mma_f16(acc[mi][ni], a[mi], bh[ni]);
        }
    }
    __syncthreads();
}

// ---------------------------------------------------------------------------
__global__ void k_init() {
    if (threadIdx.x < 8) g_acc[threadIdx.x] = 0.0;
}

// Xp (B,D,T) t-fastest -> fp16 [t][b][d] + fp32 X20 [b][d]
__global__ void k_conv_x(const float* __restrict__ Xp) {
    int idx = blockIdx.x * blockDim.x + threadIdx.x;
    if (idx >= BB * DD) return;
    const float* s = Xp + (size_t)idx * TT;
#pragma unroll
    for (int t = 0; t < TT; t++) {
        const float v = s[t];
        g_X16[(size_t)t * BB * DD + idx] = __float2half_rn(v);
        if (t == TAUV) g_X20[idx] = v;
    }
}

// F_enc (D,H) -> transposed fp16 [h][d]
__global__ void k_conv_fe(const float* __restrict__ Fe) {
    __shared__ float tile[32][33];
    const int d0 = blockIdx.x * 32, h0 = blockIdx.y * 32;
    for (int r = threadIdx.y; r < 32; r += 8)
        tile[r][threadIdx.x] = Fe[(size_t)(d0 + r) * HH + h0 + threadIdx.x];
    __syncthreads();
    for (int r = threadIdx.y; r < 32; r += 8)
        g_Fe16[(size_t)(h0 + r) * DD + d0 + threadIdx.x] =
            __float2half_rn(tile[threadIdx.x][r]);
}

// F_dec (H,D) -> transposed fp16 [d][h]
__global__ void k_conv_fd(const float* __restrict__ Fd) {
    __shared__ float tile[32][33];
    const int h0 = blockIdx.x * 32, d0 = blockIdx.y * 32;
    for (int r = threadIdx.y; r < 32; r += 8)
        tile[r][threadIdx.x] = Fd[(size_t)(h0 + r) * DD + d0 + threadIdx.x];
    __syncthreads();
    for (int r = threadIdx.y; r < 32; r += 8)
        g_Fd16[(size_t)(d0 + r) * HH + h0 + threadIdx.x] =
            __float2half_rn(tile[threadIdx.x][r]);
}

// ---------------------------------------------------------------------------
// GEMM 1 (fp16) + distributed convB streaming:
//   phase 1: Zp[t] = X[t] (B x D) @ F_enc^T; fp16 Zp into k_zt A layout
//            (flip baked in) + fp32 Zlast @ t=20.
//   phase 2: this CTA streams its 1/2688 share of Bs/tril(M,1) -> g_B16
//            (fp16, k_zt B layout) with fused |Bs| / |M| sums. MLP=8.
// ---------------------------------------------------------------------------
__global__ void __launch_bounds__(256, 1) k_zp_convB(const float* __restrict__ Bsw,
                                                     const float* __restrict__ Mw) {
    extern __shared__ char smem[];
    const int tid = threadIdx.x;
    const int lane = tid & 31, warp = tid >> 5;
    const int wm = warp & 1, wn = warp >> 1;
    const int t = blockIdx.z;
    const int m0 = blockIdx.y * 128, n0 = blockIdx.x * 128;

    float acc[4][4][4] = {};
    mma_mainloop_f16<DD>(g_X16 + ((size_t)t * BB + m0) * DD, DD,
                         g_Fe16 + (size_t)n0 * DD, DD,
                         smem, acc);

    const int layer = (t < TAUV) ? (TAUV - 1 - t) : TAUV;
    const int mb = m0 + wm * 64 + (lane >> 2);
    const int nb = n0 + wn * 32 + (lane & 3) * 2;
#pragma unroll
    for (int mi = 0; mi < 4; mi++)
#pragma unroll
        for (int ni = 0; ni < 4; ni++)
#pragma unroll
            for (int half = 0; half < 2; half++) {
                const int m = mb + mi * 16 + half * 8;
                const int n = nb + ni * 8;
                const float f0 = acc[mi][ni][half * 2];
                const float f1 = acc[mi][ni][half * 2 + 1];
                const size_t o = (size_t)m * KTOT + (size_t)layer * HH + n;
                *(__half2*)(g_A16 + o) = __floats2half2_rn(f0, f1);
                if (t == TAUV)
                    *(float2*)(g_Zlast + (size_t)m * HH + n) = make_float2(f0, f1);
            }

    // ---- phase 2: convB streaming (4096 units of 128 B per CTA) ----
    // unit u -> d32 = u & 127 (32-float block), h = (u>>7) & 4095, l = u >> 19.
    const int zidx = blockIdx.x + 32 * blockIdx.y + 128 * blockIdx.z;  // 0..2687
    const size_t u0 = (size_t)zidx * 4096;
    float sBs = 0.f, sM = 0.f;
#pragma unroll 1
    for (int it = 0; it < 16; it++) {
        const size_t u = u0 + it * 256 + tid;
        const int d32 = (int)(u & 127);
        const int h   = (int)((u >> 7) & 4095);
        const int l   = (int)(u >> 19);
        const bool isM = (l == TAUV);
        const float* src = isM ? (Mw + ((size_t)h * HH + d32 * 32))
                               : (Bsw + (((size_t)l * HH + h) * HH + d32 * 32));
        float4 v[8];
#pragma unroll
        for (int j = 0; j < 8; j++) v[j] = __ldcs((const float4*)src + j);
        if (isM) {
#pragma unroll
            for (int j = 0; j < 8; j++) {
                float* e = (float*)&v[j];
#pragma unroll
                for (int c = 0; c < 4; c++)
                    if (d32 * 32 + j * 4 + c > h + 1) e[c] = 0.f;
                sM += fabsf(e[0]) + fabsf(e[1]) + fabsf(e[2]) + fabsf(e[3]);
            }
        } else {
#pragma unroll
            for (int j = 0; j < 8; j++)
                sBs += fabsf(v[j].x) + fabsf(v[j].y) + fabsf(v[j].z) + fabsf(v[j].w);
        }
        __half* dst = g_B16 + (size_t)h * KTOT + (size_t)l * HH + d32 * 32;
#pragma unroll
        for (int j = 0; j < 4; j++) {
            union { __half2 b; uint32_t u; } p0, p1, p2, p3;
            p0.b = __floats2half2_rn(v[2*j].x,   v[2*j].y);
            p1.b = __floats2half2_rn(v[2*j].z,   v[2*j].w);
            p2.b = __floats2half2_rn(v[2*j+1].x, v[2*j+1].y);
            p3.b = __floats2half2_rn(v[2*j+1].z, v[2*j+1].w);
            *(uint4*)(dst + j * 8) = make_uint4(p0.u, p1.u, p2.u, p3.u);
        }
    }
    // block-reduce the two abs-sums (smem stages are dead; reuse as scratch)
    float* red = (float*)smem;
    red[tid] = sBs; __syncthreads();
    for (int s = 128; s; s >>= 1) { if (tid < s) red[tid] += red[tid + s]; __syncthreads(); }
    if (tid == 0 && red[0] != 0.f) atomicAdd(&g_acc[0], (double)red[0]);
    __syncthreads();
    red[tid] = sM; __syncthreads();
    for (int s = 128; s; s >>= 1) { if (tid < s) red[tid] += red[tid + s]; __syncthreads(); }
    if (tid == 0 && red[0] != 0.f) atomicAdd(&g_acc[1], (double)red[0]);
}

// ---------------------------------------------------------------------------
// GEMM 2 (fp16, fused): Zt (B x H) over K = 21*4096.
// ---------------------------------------------------------------------------
__global__ void __launch_bounds__(256, 1) k_zt_f16() {
    extern __shared__ char smem[];
    const int tid = threadIdx.x;
    const int lane = tid & 31, warp = tid >> 5;
    const int wm = warp & 1, wn = warp >> 1;
    const int m0 = blockIdx.y * 128, n0 = blockIdx.x * 128;

    float acc[4][4][4] = {};
    mma_mainloop_f16<KTOT>(g_A16 + (size_t)m0 * KTOT, KTOT,
                           g_B16 + (size_t)n0 * KTOT, KTOT,
                           smem, acc);

    const int mb = m0 + wm * 64 + (lane >> 2);
    const int nb = n0 + wn * 32 + (lane & 3) * 2;
#pragma unroll
    for (int mi = 0; mi < 4; mi++)
#pragma unroll
        for (int ni = 0; ni < 4; ni++)
#pragma unroll
            for (int half = 0; half < 2; half++) {
                const int m = mb + mi * 16 + half * 8;
                const int n = nb + ni * 8;
                *(float2*)(g_Zt + (size_t)m * HH + n) =
                    make_float2(acc[mi][ni][half * 2], acc[mi][ni][half * 2 + 1]);
            }
}

// ---------------------------------------------------------------------------
// GEMM 3 (fp16, fused SSE): recons = Zp[20] (B x H) @ F_dec^T (D x H)^T,
// compared against X20 in fp32; only the SSE leaves the kernel.
// ---------------------------------------------------------------------------
__global__ void __launch_bounds__(256, 1) k_recons_f16() {
    extern __shared__ char smem[];
    const int tid = threadIdx.x;
    const int lane = tid & 31, warp = tid >> 5;
    const int wm = warp & 1, wn = warp >> 1;
    const int m0 = blockIdx.y * 128, n0 = blockIdx.x * 128;
    __shared__ float red[256];

    float acc[4][4][4] = {};
    mma_mainloop_f16<HH>(g_A16 + (size_t)m0 * KTOT + (size_t)TAUV * HH, KTOT,
                         g_Fd16 + (size_t)n0 * HH, HH,
                         smem, acc);

    const int mb = m0 + wm * 64 + (lane >> 2);
    const int nb = n0 + wn * 32 + (lane & 3) * 2;
    float sse = 0.f;
#pragma unroll
    for (int mi = 0; mi < 4; mi++)
#pragma unroll
        for (int ni = 0; ni < 4; ni++)
#pragma unroll
            for (int half = 0; half < 2; half++) {
                const int m = mb + mi * 16 + half * 8;
                const int n = nb + ni * 8;
                const float2 x = *(const float2*)(g_X20 + (size_t)m * DD + n);
                const float d0 = acc[mi][ni][half * 2] - x.x;
                const float d1 = acc[mi][ni][half * 2 + 1] - x.y;
                sse += d0 * d0 + d1 * d1;
            }
    red[tid] = sse; __syncthreads();
    for (int s = 128; s; s >>= 1) { if (tid < s) red[tid] += red[tid + s]; __syncthreads(); }
    if (tid == 0) atomicAdd(&g_acc[2], (double)red[0]);
}

// ---------------------------------------------------------------------------
// Per-row exact top-100 via 8-bit radix select on |Zt|, then masked losses.
// ---------------------------------------------------------------------------
__global__ void __launch_bounds__(256) k_topk() {
    __shared__ float    zrow[HH];
    __shared__ unsigned hist[256];
    __shared__ unsigned s_prefix;
    __shared__ int      s_k;
    __shared__ float    red[256];

    const int b = blockIdx.x, tid = threadIdx.x;
    const float* zt = g_Zt + (size_t)b * HH;
    const float* zl = g_Zlast + (size_t)b * HH;

    for (int i = tid; i < HH; i += 256) zrow[i] = zt[i];
    __syncthreads();

    unsigned prefix = 0u;
    int kneed = KTOP;
    for (int shift = 24; shift >= 0; shift -= 8) {
        hist[tid] = 0u;
        __syncthreads();
        const unsigned hm = (shift == 24) ? 0u : (0xFFFFFFFFu << (shift + 8));
        for (int i = tid; i < HH; i += 256) {
            const unsigned bits = __float_as_uint(fabsf(zrow[i]));
            if ((bits & hm) == prefix) atomicAdd(&hist[(bits >> shift) & 255u], 1u);
        }
        __syncthreads();
        if (tid == 0) {
            int acc = 0;
            for (int bb = 255; bb >= 0; bb--) {
                acc += (int)hist[bb];
                if (acc >= kneed) {
                    s_prefix = prefix | ((unsigned)bb << shift);
                    s_k = kneed - (acc - (int)hist[bb]);
                    break;
                }
            }
        }
        __syncthreads();
        prefix = s_prefix;
        kneed = s_k;
        __syncthreads();
    }
    const unsigned T = prefix;
    if (tid == 0) {
        int r = kneed;
        for (int i = 0; i < HH; i++) {
            if (__float_as_uint(fabsf(zrow[i])) == T) {
                if (r > 0) r--; else zrow[i] = 0.f;
            }
        }
    }
    __syncthreads();

    float sse = 0.f, sab = 0.f, saz = 0.f;
    for (int i = tid; i < HH; i += 256) {
        const float z  = zrow[i];
        const float zm = (__float_as_uint(fabsf(z)) >= T) ? z : 0.f;
        const float zv = zl[i];
        const float d  = zm - zv;
        sse += d * d;
        sab += fabsf(d);
        saz += fabsf(zm);
    }
    red[tid] = sse; __syncthreads();
    for (int s = 128; s; s >>= 1) { if (tid < s) red[tid] += red[tid + s]; __syncthreads(); }
    if (tid == 0) atomicAdd(&g_acc[3], (double)red[0]);
    __syncthreads();
    red[tid] = sab; __syncthreads();
    for (int s = 128; s; s >>= 1) { if (tid < s) red[tid] += red[tid + s]; __syncthreads(); }
    if (tid == 0) atomicAdd(&g_acc[4], (double)red[0]);
    __syncthreads();
    red[tid] = saz; __syncthreads();
    for (int s = 128; s; s >>= 1) { if (tid < s) red[tid] += red[tid + s]; __syncthreads(); }
    if (tid == 0) atomicAdd(&g_acc[5], (double)red[0]);
}

// ---------------------------------------------------------------------------
__global__ void k_final(float* __restrict__ out) {
    if (threadIdx.x == 0 && blockIdx.x == 0) {
        out[0] = (float)(g_acc[2] / ((double)BB * DD));
        out[1] = (float)(g_acc[3] / ((double)BB * HH));
        out[2] = (float)(g_acc[4] / ((double)BB * HH));
        out[3] = (float)(g_acc[0] / ((double)HH * HH));
        out[4] = (float)(g_acc[1] / ((double)HH * HH));
        out[5] = (float)(g_acc[5] / ((double)BB * HH));
    }
}

// ---------------------------------------------------------------------------
extern "C" void kernel_launch(void* const* d_in, const int* in_sizes, int n_in,
                              void* d_out, int out_size) {
    (void)in_sizes; (void)n_in; (void)out_size;
    const float* Xp  = (const float*)d_in[0];
    const float* Fe  = (const float*)d_in[1];
    const float* Fd  = (const float*)d_in[2];
    const float* Bsw = (const float*)d_in[3];
    const float* Mw  = (const float*)d_in[4];
    float* out = (float*)d_out;

    cudaFuncSetAttribute(k_zp_convB,   cudaFuncAttributeMaxDynamicSharedMemorySize, SMEM_MMA);
    cudaFuncSetAttribute(k_zt_f16,     cudaFuncAttributeMaxDynamicSharedMemorySize, SMEM_MMA);
    cudaFuncSetAttribute(k_recons_f16, cudaFuncAttributeMaxDynamicSharedMemorySize, SMEM_MMA);

    k_init<<<1, 32>>>();
    k_conv_x<<<(BB * DD + 255) / 256, 256>>>(Xp);
    k_conv_fe<<<dim3(DD / 32, HH / 32), dim3(32, 8)>>>(Fe);
    k_conv_fd<<<dim3(HH / 32, DD / 32), dim3(32, 8)>>>(Fd);

    k_zp_convB<<<dim3(HH / 128, BB / 128, TT), 256, SMEM_MMA>>>(Bsw, Mw);
    k_zt_f16<<<dim3(HH / 128, BB / 128), 256, SMEM_MMA>>>();
    k_recons_f16<<<dim3(DD / 128, BB / 128), 256, SMEM_MMA>>>();

    k_topk<<<BB, 256>>>();
    k_final<<<1, 32>>>(out);
}

// round 12
// speedup vs baseline: 1.0666x; 1.0666x over previous
#include <cuda_runtime.h>
#include <cuda_fp16.h>
#include <cstdint>
#include <math.h>

// Problem constants
#define BB   512
#define DD   1024
#define HH   4096
#define TT   21
#define TAUV 20
#define KTOP 100
#define KTOT (TT * HH)        // 86016
#define BK   32
#define SST  40               // smem k-stride in halves (80 B, ldmatrix-friendly)
#define TEN_BYTES (128 * SST * 2)     // 10240 B per tensor per stage
#define STG  (2 * TEN_BYTES)          // A|B per stage = 20480
#define NST  4
#define SMEM_MMA (NST * STG)          // 81920

// ---------------------------------------------------------------------------
// Static device scratch (no allocations allowed)
// ---------------------------------------------------------------------------
__device__ __half g_X16[(size_t)TT * BB * DD];   // X fp16 [t][b][d]
__device__ float  g_X20[(size_t)BB * DD];        // X[:,:,20] fp32 compact
__device__ __half g_Fe16[(size_t)HH * DD];       // F_enc^T fp16 [h][d]
__device__ __half g_Fd16[(size_t)DD * HH];       // F_dec^T fp16 [d][h]
__device__ __half g_A16[(size_t)BB * KTOT];      // Zp fp16 [b][layer*H+h']
__device__ __half g_B16[(size_t)HH * KTOT];      // Bs/trilM fp16 [h][layer*H+d]
__device__ float g_Zlast[(size_t)BB * HH];       // fp32 Z_last (from k_zp t=20)
__device__ float g_Zt   [(size_t)BB * HH];
// 0=sum|Bs| 1=sum|trilM| 2=sseX 3=sseZ 4=sumAbsE 5=sum|Zt|
__device__ double g_acc[8];

// ---------------------------------------------------------------------------
// PTX helpers (base-target only: cp.async / ldmatrix / mma.sync)
// ---------------------------------------------------------------------------
__device__ __forceinline__ uint32_t smem_u32(const void* p) {
    uint32_t a;
    asm("{ .reg .u64 t; cvta.to.shared.u64 t, %1; cvt.u32.u64 %0, t; }"
        : "=r"(a) : "l"(p));
    return a;
}
__device__ __forceinline__ void cp_async16(uint32_t saddr, const void* gaddr) {
    asm volatile("cp.async.cg.shared.global [%0], [%1], 16;"
                 :: "r"(saddr), "l"(gaddr) : "memory");
}
__device__ __forceinline__ void cp_commit() {
    asm volatile("cp.async.commit_group;" ::: "memory");
}
__device__ __forceinline__ void cp_wait2() {
    asm volatile("cp.async.wait_group 2;" ::: "memory");
}
__device__ __forceinline__ void cp_wait1() {
    asm volatile("cp.async.wait_group 1;" ::: "memory");
}
__device__ __forceinline__ void cp_wait0() {
    asm volatile("cp.async.wait_group 0;" ::: "memory");
}
__device__ __forceinline__ void ldsm_x4(uint32_t* r, uint32_t addr) {
    asm volatile("ldmatrix.sync.aligned.m8n8.x4.shared.b16 {%0,%1,%2,%3}, [%4];"
                 : "=r"(r[0]), "=r"(r[1]), "=r"(r[2]), "=r"(r[3]) : "r"(addr));
}
__device__ __forceinline__ void mma_f16(float* c, const uint32_t* a, const uint32_t* b) {
    asm volatile(
        "mma.sync.aligned.m16n8k16.row.col.f32.f16.f16.f32 "
        "{%0,%1,%2,%3}, {%4,%5,%6,%7}, {%8,%9}, {%0,%1,%2,%3};"
        : "+f"(c[0]), "+f"(c[1]), "+f"(c[2]), "+f"(c[3])
        : "r"(a[0]), "r"(a[1]), "r"(a[2]), "r"(a[3]), "r"(b[0]), "r"(b[1]));
}

// ---------------------------------------------------------------------------
// fp16 1-term mainloop: acc += A*B over K = KT (per-row strides strA/strB).
// CTA 128x128, 8 warps (2m x 4n), warp tile 64x32, BK=32, 4-stage cp.async,
// single __syncthreads per chunk (stage reuse is post-barrier safe).
// [R10 configuration — 80 KB smem, 2 CTAs/SM]
// ---------------------------------------------------------------------------
template <int KT>
__device__ __forceinline__ void mma_mainloop_f16(
    const __half* __restrict__ A, size_t strA,
    const __half* __restrict__ B, size_t strB,
    char* smem, float acc[4][4][4])
{
    const int tid  = threadIdx.x;
    const int lane = tid & 31, warp = tid >> 5;
    const int wm = warp & 1, wn = warp >> 1;
    const uint32_t sbase = smem_u32(smem);

    const int lrow = tid >> 1;
    const int lk   = (tid & 1) * 16;
    const size_t growA = (size_t)lrow * strA + lk;
    const size_t growB = (size_t)lrow * strB + lk;
    constexpr int NKT = KT / BK;

    auto issue = [&](int kt) {
        const int s = kt & (NST - 1);
        const size_t ka = growA + (size_t)kt * BK;
        const size_t kb = growB + (size_t)kt * BK;
        const uint32_t so = sbase + s * STG + (lrow * SST + lk) * 2;
        cp_async16(so,                  A + ka);
        cp_async16(so + 16,             A + ka + 8);
        cp_async16(so + TEN_BYTES,      B + kb);
        cp_async16(so + TEN_BYTES + 16, B + kb + 8);
        cp_commit();
    };

    issue(0); issue(1); issue(2);

    const int arow = lane & 15, akc = (lane >> 4) * 8;
    const int brow = lane & 15, bkc = (lane >> 4) * 8;

    for (int kt = 0; kt < NKT; kt++) {
        if (kt + 2 < NKT)      cp_wait2();
        else if (kt + 1 < NKT) cp_wait1();
        else                   cp_wait0();
        __syncthreads();
        if (kt + 3 < NKT) issue(kt + 3);   // overwrites stage (kt-1)&3: safe post-barrier

        const uint32_t tb = sbase + (kt & (NST - 1)) * STG;
#pragma unroll
        for (int kk = 0; kk < 2; kk++) {
            uint32_t a[4][4], bh[4][2];
#pragma unroll
            for (int mi = 0; mi < 4; mi++)
                ldsm_x4(a[mi], tb + ((wm * 64 + mi * 16 + arow) * SST + kk * 16 + akc) * 2);
#pragma unroll
            for (int p = 0; p < 2; p++) {
                uint32_t r[4];
                ldsm_x4(r, tb + TEN_BYTES +
                        ((wn * 32 + p * 16 + brow) * SST + kk * 16 + bkc) * 2);
                bh[2 * p][0] = r[0];     bh[2 * p][1] = r[2];
                bh[2 * p + 1][0] = r[1]; bh[2 * p + 1][1] = r[3];
            }
#pragma unroll
            for (int mi = 0; mi < 4; mi++)
#pragma unroll
                for (int ni = 0; ni < 4; ni++)
                    mma_f16(acc[mi][ni], a[mi], bh[ni]);
        }
    }
    __syncthreads();
}

// ---------------------------------------------------------------------------
__global__ void k_init() {
    if (threadIdx.x < 8) g_acc[threadIdx.x] = 0.0;
}

// Xp (B,D,T) t-fastest -> fp16 [t][b][d] + fp32 X20 [b][d]
__global__ void k_conv_x(const float* __restrict__ Xp) {
    int idx = blockIdx.x * blockDim.x + threadIdx.x;
    if (idx >= BB * DD) return;
    const float* s = Xp + (size_t)idx * TT;
#pragma unroll
    for (int t = 0; t < TT; t++) {
        const float v = s[t];
        g_X16[(size_t)t * BB * DD + idx] = __float2half_rn(v);
        if (t == TAUV) g_X20[idx] = v;
    }
}

// F_enc (D,H) -> transposed fp16 [h][d]
__global__ void k_conv_fe(const float* __restrict__ Fe) {
    __shared__ float tile[32][33];
    const int d0 = blockIdx.x * 32, h0 = blockIdx.y * 32;
    for (int r = threadIdx.y; r < 32; r += 8)
        tile[r][threadIdx.x] = Fe[(size_t)(d0 + r) * HH + h0 + threadIdx.x];
    __syncthreads();
    for (int r = threadIdx.y; r < 32; r += 8)
        g_Fe16[(size_t)(h0 + r) * DD + d0 + threadIdx.x] =
            __float2half_rn(tile[threadIdx.x][r]);
}

// F_dec (H,D) -> transposed fp16 [d][h]
__global__ void k_conv_fd(const float* __restrict__ Fd) {
    __shared__ float tile[32][33];
    const int h0 = blockIdx.x * 32, d0 = blockIdx.y * 32;
    for (int r = threadIdx.y; r < 32; r += 8)
        tile[r][threadIdx.x] = Fd[(size_t)(h0 + r) * DD + d0 + threadIdx.x];
    __syncthreads();
    for (int r = threadIdx.y; r < 32; r += 8)
        g_Fd16[(size_t)(d0 + r) * HH + h0 + threadIdx.x] =
            __float2half_rn(tile[threadIdx.x][r]);
}

// ---------------------------------------------------------------------------
// GEMM 1 (fp16, R10 mainloop) + distributed convB streaming:
//   phase 1: Zp[t] = X[t] (B x D) @ F_enc^T; fp16 Zp into k_zt A layout
//            (flip baked in) + fp32 Zlast @ t=20.
//   phase 2: this CTA streams its 1/2688 share of Bs/tril(M,1) -> g_B16
//            with fused |Bs| / |M| sums.
// ---------------------------------------------------------------------------
__global__ void __launch_bounds__(256) k_zp_convB(const float* __restrict__ Bsw,
                                                  const float* __restrict__ Mw) {
    extern __shared__ char smem[];
    const int tid = threadIdx.x;
    const int lane = tid & 31, warp = tid >> 5;
    const int wm = warp & 1, wn = warp >> 1;
    const int t = blockIdx.z;
    const int m0 = blockIdx.y * 128, n0 = blockIdx.x * 128;

    float acc[4][4][4] = {};
    mma_mainloop_f16<DD>(g_X16 + ((size_t)t * BB + m0) * DD, DD,
                         g_Fe16 + (size_t)n0 * DD, DD,
                         smem, acc);

    const int layer = (t < TAUV) ? (TAUV - 1 - t) : TAUV;
    const int mb = m0 + wm * 64 + (lane >> 2);
    const int nb = n0 + wn * 32 + (lane & 3) * 2;
#pragma unroll
    for (int mi = 0; mi < 4; mi++)
#pragma unroll
        for (int ni = 0; ni < 4; ni++)
#pragma unroll
            for (int half = 0; half < 2; half++) {
                const int m = mb + mi * 16 + half * 8;
                const int n = nb + ni * 8;
                const float f0 = acc[mi][ni][half * 2];
                const float f1 = acc[mi][ni][half * 2 + 1];
                const size_t o = (size_t)m * KTOT + (size_t)layer * HH + n;
                *(__half2*)(g_A16 + o) = __floats2half2_rn(f0, f1);
                if (t == TAUV)
                    *(float2*)(g_Zlast + (size_t)m * HH + n) = make_float2(f0, f1);
            }

    // ---- phase 2: convB streaming (4096 units of 128 B per CTA) ----
    // unit u -> d32 = u & 127 (32-float block), h = (u>>7) & 4095, l = u >> 19.
    const int zidx = blockIdx.x + 32 * blockIdx.y + 128 * blockIdx.z;  // 0..2687
    const size_t u0 = (size_t)zidx * 4096;
    float sBs = 0.f, sM = 0.f;
#pragma unroll 1
    for (int it = 0; it < 16; it++) {
        const size_t u = u0 + it * 256 + tid;
        const int d32 = (int)(u & 127);
        const int h   = (int)((u >> 7) & 4095);
        const int l   = (int)(u >> 19);
        const bool isM = (l == TAUV);
        const float* src = isM ? (Mw + ((size_t)h * HH + d32 * 32))
                               : (Bsw + (((size_t)l * HH + h) * HH + d32 * 32));
        __half* dst = g_B16 + (size_t)h * KTOT + (size_t)l * HH + d32 * 32;
#pragma unroll 1
        for (int half = 0; half < 2; half++) {
            float4 v[4];
#pragma unroll
            for (int j = 0; j < 4; j++)
                v[j] = __ldcs((const float4*)src + half * 4 + j);
            if (isM) {
#pragma unroll
                for (int j = 0; j < 4; j++) {
                    float* e = (float*)&v[j];
#pragma unroll
                    for (int c = 0; c < 4; c++)
                        if (d32 * 32 + half * 16 + j * 4 + c > h + 1) e[c] = 0.f;
                    sM += fabsf(e[0]) + fabsf(e[1]) + fabsf(e[2]) + fabsf(e[3]);
                }
            } else {
#pragma unroll
                for (int j = 0; j < 4; j++)
                    sBs += fabsf(v[j].x) + fabsf(v[j].y) + fabsf(v[j].z) + fabsf(v[j].w);
            }
#pragma unroll
            for (int j = 0; j < 2; j++) {
                union { __half2 b; uint32_t u; } p0, p1, p2, p3;
                p0.b = __floats2half2_rn(v[2*j].x,   v[2*j].y);
                p1.b = __floats2half2_rn(v[2*j].z,   v[2*j].w);
                p2.b = __floats2half2_rn(v[2*j+1].x, v[2*j+1].y);
                p3.b = __floats2half2_rn(v[2*j+1].z, v[2*j+1].w);
                *(uint4*)(dst + half * 16 + j * 8) = make_uint4(p0.u, p1.u, p2.u, p3.u);
            }
        }
    }
    // block-reduce the two abs-sums (smem stages are dead; reuse as scratch)
    float* red = (float*)smem;
    red[tid] = sBs; __syncthreads();
    for (int s = 128; s; s >>= 1) { if (tid < s) red[tid] += red[tid + s]; __syncthreads(); }
    if (tid == 0 && red[0] != 0.f) atomicAdd(&g_acc[0], (double)red[0]);
    __syncthreads();
    red[tid] = sM; __syncthreads();
    for (int s = 128; s; s >>= 1) { if (tid < s) red[tid] += red[tid + s]; __syncthreads(); }
    if (tid == 0 && red[0] != 0.f) atomicAdd(&g_acc[1], (double)red[0]);
}

// ---------------------------------------------------------------------------
// GEMM 2 (fp16, fused): Zt (B x H) over K = 21*4096.
// ---------------------------------------------------------------------------
__global__ void __launch_bounds__(256) k_zt_f16() {
    extern __shared__ char smem[];
    const int tid = threadIdx.x;
    const int lane = tid & 31, warp = tid >> 5;
    const int wm = warp & 1, wn = warp >> 1;
    const int m0 = blockIdx.y * 128, n0 = blockIdx.x * 128;

    float acc[4][4][4] = {};
    mma_mainloop_f16<KTOT>(g_A16 + (size_t)m0 * KTOT, KTOT,
                           g_B16 + (size_t)n0 * KTOT, KTOT,
                           smem, acc);

    const int mb = m0 + wm * 64 + (lane >> 2);
    const int nb = n0 + wn * 32 + (lane & 3) * 2;
#pragma unroll
    for (int mi = 0; mi < 4; mi++)
#pragma unroll
        for (int ni = 0; ni < 4; ni++)
#pragma unroll
            for (int half = 0; half < 2; half++) {
                const int m = mb + mi * 16 + half * 8;
                const int n = nb + ni * 8;
                *(float2*)(g_Zt + (size_t)m * HH + n) =
                    make_float2(acc[mi][ni][half * 2], acc[mi][ni][half * 2 + 1]);
            }
}

// ---------------------------------------------------------------------------
// GEMM 3 (fp16, fused SSE): recons = Zp[20] (B x H) @ F_dec^T (D x H)^T,
// compared against X20 in fp32; only the SSE leaves the kernel.
// ---------------------------------------------------------------------------
__global__ void __launch_bounds__(256) k_recons_f16() {
    extern __shared__ char smem[];
    const int tid = threadIdx.x;
    const int lane = tid & 31, warp = tid >> 5;
    const int wm = warp & 1, wn = warp >> 1;
    const int m0 = blockIdx.y * 128, n0 = blockIdx.x * 128;
    __shared__ float red[256];

    float acc[4][4][4] = {};
    mma_mainloop_f16<HH>(g_A16 + (size_t)m0 * KTOT + (size_t)TAUV * HH, KTOT,
                         g_Fd16 + (size_t)n0 * HH, HH,
                         smem, acc);

    const int mb = m0 + wm * 64 + (lane >> 2);
    const int nb = n0 + wn * 32 + (lane & 3) * 2;
    float sse = 0.f;
#pragma unroll
    for (int mi = 0; mi < 4; mi++)
#pragma unroll
        for (int ni = 0; ni < 4; ni++)
#pragma unroll
            for (int half = 0; half < 2; half++) {
                const int m = mb + mi * 16 + half * 8;
                const int n = nb + ni * 8;
                const float2 x = *(const float2*)(g_X20 + (size_t)m * DD + n);
                const float d0 = acc[mi][ni][half * 2] - x.x;
                const float d1 = acc[mi][ni][half * 2 + 1] - x.y;
                sse += d0 * d0 + d1 * d1;
            }
    red[tid] = sse; __syncthreads();
    for (int s = 128; s; s >>= 1) { if (tid < s) red[tid] += red[tid + s]; __syncthreads(); }
    if (tid == 0) atomicAdd(&g_acc[2], (double)red[0]);
}

// ---------------------------------------------------------------------------
// Per-row exact top-100 via 8-bit radix select on |Zt|, then masked losses.
// ---------------------------------------------------------------------------
__global__ void __launch_bounds__(256) k_topk() {
    __shared__ float    zrow[HH];
    __shared__ unsigned hist[256];
    __shared__ unsigned s_prefix;
    __shared__ int      s_k;
    __shared__ float    red[256];

    const int b = blockIdx.x, tid = threadIdx.x;
    const float* zt = g_Zt + (size_t)b * HH;
    const float* zl = g_Zlast + (size_t)b * HH;

    for (int i = tid; i < HH; i += 256) zrow[i] = zt[i];
    __syncthreads();

    unsigned prefix = 0u;
    int kneed = KTOP;
    for (int shift = 24; shift >= 0; shift -= 8) {
        hist[tid] = 0u;
        __syncthreads();
        const unsigned hm = (shift == 24) ? 0u : (0xFFFFFFFFu << (shift + 8));
        for (int i = tid; i < HH; i += 256) {
            const unsigned bits = __float_as_uint(fabsf(zrow[i]));
            if ((bits & hm) == prefix) atomicAdd(&hist[(bits >> shift) & 255u], 1u);
        }
        __syncthreads();
        if (tid == 0) {
            int acc = 0;
            for (int bb = 255; bb >= 0; bb--) {
                acc += (int)hist[bb];
                if (acc >= kneed) {
                    s_prefix = prefix | ((unsigned)bb << shift);
                    s_k = kneed - (acc - (int)hist[bb]);
                    break;
                }
            }
        }
        __syncthreads();
        prefix = s_prefix;
        kneed = s_k;
        __syncthreads();
    }
    const unsigned T = prefix;
    if (tid == 0) {
        int r = kneed;
        for (int i = 0; i < HH; i++) {
            if (__float_as_uint(fabsf(zrow[i])) == T) {
                if (r > 0) r--; else zrow[i] = 0.f;
            }
        }
    }
    __syncthreads();

    float sse = 0.f, sab = 0.f, saz = 0.f;
    for (int i = tid; i < HH; i += 256) {
        const float z  = zrow[i];
        const float zm = (__float_as_uint(fabsf(z)) >= T) ? z : 0.f;
        const float zv = zl[i];
        const float d  = zm - zv;
        sse += d * d;
        sab += fabsf(d);
        saz += fabsf(zm);
    }
    red[tid] = sse; __syncthreads();
    for (int s = 128; s; s >>= 1) { if (tid < s) red[tid] += red[tid + s]; __syncthreads(); }
    if (tid == 0) atomicAdd(&g_acc[3], (double)red[0]);
    __syncthreads();
    red[tid] = sab; __syncthreads();
    for (int s = 128; s; s >>= 1) { if (tid < s) red[tid] += red[tid + s]; __syncthreads(); }
    if (tid == 0) atomicAdd(&g_acc[4], (double)red[0]);
    __syncthreads();
    red[tid] = saz; __syncthreads();
    for (int s = 128; s; s >>= 1) { if (tid < s) red[tid] += red[tid + s]; __syncthreads(); }
    if (tid == 0) atomicAdd(&g_acc[5], (double)red[0]);
}

// ---------------------------------------------------------------------------
__global__ void k_final(float* __restrict__ out) {
    if (threadIdx.x == 0 && blockIdx.x == 0) {
        out[0] = (float)(g_acc[2] / ((double)BB * DD));
        out[1] = (float)(g_acc[3] / ((double)BB * HH));
        out[2] = (float)(g_acc[4] / ((double)BB * HH));
        out[3] = (float)(g_acc[0] / ((double)HH * HH));
        out[4] = (float)(g_acc[1] / ((double)HH * HH));
        out[5] = (float)(g_acc[5] / ((double)BB * HH));
    }
}

// ---------------------------------------------------------------------------
extern "C" void kernel_launch(void* const* d_in, const int* in_sizes, int n_in,
                              void* d_out, int out_size) {
    (void)in_sizes; (void)n_in; (void)out_size;
    const float* Xp  = (const float*)d_in[0];
    const float* Fe  = (const float*)d_in[1];
    const float* Fd  = (const float*)d_in[2];
    const float* Bsw = (const float*)d_in[3];
    const float* Mw  = (const float*)d_in[4];
    float* out = (float*)d_out;

    cudaFuncSetAttribute(k_zp_convB,   cudaFuncAttributeMaxDynamicSharedMemorySize, SMEM_MMA);
    cudaFuncSetAttribute(k_zt_f16,     cudaFuncAttributeMaxDynamicSharedMemorySize, SMEM_MMA);
    cudaFuncSetAttribute(k_recons_f16, cudaFuncAttributeMaxDynamicSharedMemorySize, SMEM_MMA);

    k_init<<<1, 32>>>();
    k_conv_x<<<(BB * DD + 255) / 256, 256>>>(Xp);
    k_conv_fe<<<dim3(DD / 32, HH / 32), dim3(32, 8)>>>(Fe);
    k_conv_fd<<<dim3(HH / 32, DD / 32), dim3(32, 8)>>>(Fd);

    k_zp_convB<<<dim3(HH / 128, BB / 128, TT), 256, SMEM_MMA>>>(Bsw, Mw);
    k_zt_f16<<<dim3(HH / 128, BB / 128), 256, SMEM_MMA>>>();
    k_recons_f16<<<dim3(DD / 128, BB / 128), 256, SMEM_MMA>>>();

    k_topk<<<BB, 256>>>();
    k_final<<<1, 32>>>(out);
}

// round 13
// speedup vs baseline: 1.1835x; 1.1095x over previous
#include <cuda_runtime.h>
#include <cuda_fp16.h>
#include <cstdint>
#include <math.h>

// Problem constants
#define BB   512
#define DD   1024
#define HH   4096
#define TT   21
#define TAUV 20
#define KTOP 100
#define KTOT (TT * HH)        // 86016
#define KHALF (KTOT / 2)      // 43008
#define BK   32
#define SST  40               // smem k-stride in halves (80 B, ldmatrix-friendly)
#define TEN_BYTES (128 * SST * 2)     // 10240 B per tensor per stage
#define STG  (2 * TEN_BYTES)          // A|B per stage = 20480
#define NST  4
#define SMEM_MMA (NST * STG)          // 81920

// ---------------------------------------------------------------------------
// Static device scratch (no allocations allowed)
// ---------------------------------------------------------------------------
__device__ __half g_X16[(size_t)TT * BB * DD];   // X fp16 [t][b][d]
__device__ float  g_X20[(size_t)BB * DD];        // X[:,:,20] fp32 compact
__device__ __half g_Fe16[(size_t)HH * DD];       // F_enc^T fp16 [h][d]
__device__ __half g_Fd16[(size_t)DD * HH];       // F_dec^T fp16 [d][h]
__device__ __half g_A16[(size_t)BB * KTOT];      // Zp fp16 [b][layer*H+h']
__device__ __half g_B16[(size_t)HH * KTOT];      // Bs/trilM fp16 [h][layer*H+d]
__device__ float g_Zlast[(size_t)BB * HH];       // fp32 Z_last (from k_zp t=20)
__device__ float g_Zt0[(size_t)BB * HH];         // Zt partial (K half 0)
__device__ float g_Zt1[(size_t)BB * HH];         // Zt partial (K half 1)
// 0=sum|Bs| 1=sum|trilM| 2=sseX 3=sseZ 4=sumAbsE 5=sum|Zt|
__device__ double g_acc[8];

// ---------------------------------------------------------------------------
// PTX helpers (base-target only: cp.async / ldmatrix / mma.sync)
// ---------------------------------------------------------------------------
__device__ __forceinline__ uint32_t smem_u32(const void* p) {
    uint32_t a;
    asm("{ .reg .u64 t; cvta.to.shared.u64 t, %1; cvt.u32.u64 %0, t; }"
        : "=r"(a) : "l"(p));
    return a;
}
__device__ __forceinline__ void cp_async16(uint32_t saddr, const void* gaddr) {
    asm volatile("cp.async.cg.shared.global [%0], [%1], 16;"
                 :: "r"(saddr), "l"(gaddr) : "memory");
}
__device__ __forceinline__ void cp_commit() {
    asm volatile("cp.async.commit_group;" ::: "memory");
}
__device__ __forceinline__ void cp_wait2() {
    asm volatile("cp.async.wait_group 2;" ::: "memory");
}
__device__ __forceinline__ void cp_wait1() {
    asm volatile("cp.async.wait_group 1;" ::: "memory");
}
__device__ __forceinline__ void cp_wait0() {
    asm volatile("cp.async.wait_group 0;" ::: "memory");
}
__device__ __forceinline__ void ldsm_x4(uint32_t* r, uint32_t addr) {
    asm volatile("ldmatrix.sync.aligned.m8n8.x4.shared.b16 {%0,%1,%2,%3}, [%4];"
                 : "=r"(r[0]), "=r"(r[1]), "=r"(r[2]), "=r"(r[3]) : "r"(addr));
}
__device__ __forceinline__ void mma_f16(float* c, const uint32_t* a, const uint32_t* b) {
    asm volatile(
        "mma.sync.aligned.m16n8k16.row.col.f32.f16.f16.f32 "
        "{%0,%1,%2,%3}, {%4,%5,%6,%7}, {%8,%9}, {%0,%1,%2,%3};"
        : "+f"(c[0]), "+f"(c[1]), "+f"(c[2]), "+f"(c[3])
        : "r"(a[0]), "r"(a[1]), "r"(a[2]), "r"(a[3]), "r"(b[0]), "r"(b[1]));
}

// ---------------------------------------------------------------------------
// fp16 1-term mainloop: acc += A*B over K = KT (per-row strides strA/strB).
// CTA 128x128, 8 warps (2m x 4n), warp tile 64x32, BK=32, 4-stage cp.async,
// single __syncthreads per chunk.  [R10 configuration — 80 KB smem]
// ---------------------------------------------------------------------------
template <int KT>
__device__ __forceinline__ void mma_mainloop_f16(
    const __half* __restrict__ A, size_t strA,
    const __half* __restrict__ B, size_t strB,
    char* smem, float acc[4][4][4])
{
    const int tid  = threadIdx.x;
    const int lane = tid & 31, warp = tid >> 5;
    const int wm = warp & 1, wn = warp >> 1;
    const uint32_t sbase = smem_u32(smem);

    const int lrow = tid >> 1;
    const int lk   = (tid & 1) * 16;
    const size_t growA = (size_t)lrow * strA + lk;
    const size_t growB = (size_t)lrow * strB + lk;
    constexpr int NKT = KT / BK;

    auto issue = [&](int kt) {
        const int s = kt & (NST - 1);
        const size_t ka = growA + (size_t)kt * BK;
        const size_t kb = growB + (size_t)kt * BK;
        const uint32_t so = sbase + s * STG + (lrow * SST + lk) * 2;
        cp_async16(so,                  A + ka);
        cp_async16(so + 16,             A + ka + 8);
        cp_async16(so + TEN_BYTES,      B + kb);
        cp_async16(so + TEN_BYTES + 16, B + kb + 8);
        cp_commit();
    };

    issue(0); issue(1); issue(2);

    const int arow = lane & 15, akc = (lane >> 4) * 8;
    const int brow = lane & 15, bkc = (lane >> 4) * 8;

    for (int kt = 0; kt < NKT; kt++) {
        if (kt + 2 < NKT)      cp_wait2();
        else if (kt + 1 < NKT) cp_wait1();
        else                   cp_wait0();
        __syncthreads();
        if (kt + 3 < NKT) issue(kt + 3);   // overwrites stage (kt-1)&3: safe post-barrier

        const uint32_t tb = sbase + (kt & (NST - 1)) * STG;
#pragma unroll
        for (int kk = 0; kk < 2; kk++) {
            uint32_t a[4][4], bh[4][2];
#pragma unroll
            for (int mi = 0; mi < 4; mi++)
                ldsm_x4(a[mi], tb + ((wm * 64 + mi * 16 + arow) * SST + kk * 16 + akc) * 2);
#pragma unroll
            for (int p = 0; p < 2; p++) {
                uint32_t r[4];
                ldsm_x4(r, tb + TEN_BYTES +
                        ((wn * 32 + p * 16 + brow) * SST + kk * 16 + bkc) * 2);
                bh[2 * p][0] = r[0];     bh[2 * p][1] = r[2];
                bh[2 * p + 1][0] = r[1]; bh[2 * p + 1][1] = r[3];
            }
#pragma unroll
            for (int mi = 0; mi < 4; mi++)
#pragma unroll
                for (int ni = 0; ni < 4; ni++)
                    mma_f16(acc[mi][ni], a[mi], bh[ni]);
        }
    }
    __syncthreads();
}

// ---------------------------------------------------------------------------
__global__ void k_init() {
    if (threadIdx.x < 8) g_acc[threadIdx.x] = 0.0;
}

// Xp (B,D,T) t-fastest -> fp16 [t][b][d] + fp32 X20 [b][d]
__global__ void k_conv_x(const float* __restrict__ Xp) {
    int idx = blockIdx.x * blockDim.x + threadIdx.x;
    if (idx >= BB * DD) return;
    const float* s = Xp + (size_t)idx * TT;
#pragma unroll
    for (int t = 0; t < TT; t++) {
        const float v = s[t];
        g_X16[(size_t)t * BB * DD + idx] = __float2half_rn(v);
        if (t == TAUV) g_X20[idx] = v;
    }
}

// F_enc (D,H) -> transposed fp16 [h][d]
__global__ void k_conv_fe(const float* __restrict__ Fe) {
    __shared__ float tile[32][33];
    const int d0 = blockIdx.x * 32, h0 = blockIdx.y * 32;
    for (int r = threadIdx.y; r < 32; r += 8)
        tile[r][threadIdx.x] = Fe[(size_t)(d0 + r) * HH + h0 + threadIdx.x];
    __syncthreads();
    for (int r = threadIdx.y; r < 32; r += 8)
        g_Fe16[(size_t)(h0 + r) * DD + d0 + threadIdx.x] =
            __float2half_rn(tile[threadIdx.x][r]);
}

// F_dec (H,D) -> transposed fp16 [d][h]
__global__ void k_conv_fd(const float* __restrict__ Fd) {
    __shared__ float tile[32][33];
    const int h0 = blockIdx.x * 32, d0 = blockIdx.y * 32;
    for (int r = threadIdx.y; r < 32; r += 8)
        tile[r][threadIdx.x] = Fd[(size_t)(h0 + r) * DD + d0 + threadIdx.x];
    __syncthreads();
    for (int r = threadIdx.y; r < 32; r += 8)
        g_Fd16[(size_t)(d0 + r) * HH + h0 + threadIdx.x] =
            __float2half_rn(tile[threadIdx.x][r]);
}

// Bs (20,H,H) + tril(M,1) -> fp16 [h][layer*H+d], fused |Bs| / |M| sums
__global__ void __launch_bounds__(256) k_convB(const float* __restrict__ Bsw,
                                               const float* __restrict__ Mw) {
    __shared__ float red[256];
    const size_t total = (size_t)TT * HH * (HH / 4);   // float4 units
    float sBs = 0.f, sM = 0.f;
    for (size_t u = blockIdx.x * 256 + threadIdx.x; u < total;
         u += (size_t)gridDim.x * 256) {
        const int d4 = (int)(u & 1023);
        const int h  = (int)((u >> 10) & 4095);
        const int l  = (int)(u >> 22);
        float4 v;
        if (l < TAUV) {
            v = __ldcs((const float4*)(Bsw + (((size_t)l * HH + h) * HH + d4 * 4)));
            sBs += fabsf(v.x) + fabsf(v.y) + fabsf(v.z) + fabsf(v.w);
        } else {
            v = *(const float4*)(Mw + ((size_t)h * HH + d4 * 4));
            float* e = (float*)&v;
#pragma unroll
            for (int j = 0; j < 4; j++)
                if (d4 * 4 + j > h + 1) e[j] = 0.f;
            sM += fabsf(v.x) + fabsf(v.y) + fabsf(v.z) + fabsf(v.w);
        }
        union { __half2 b; uint32_t u; } p0, p1;
        p0.b = __floats2half2_rn(v.x, v.y);
        p1.b = __floats2half2_rn(v.z, v.w);
        *(uint2*)(g_B16 + (size_t)h * KTOT + (size_t)l * HH + d4 * 4) =
            make_uint2(p0.u, p1.u);
    }
    const int tid = threadIdx.x;
    red[tid] = sBs; __syncthreads();
    for (int s = 128; s; s >>= 1) { if (tid < s) red[tid] += red[tid + s]; __syncthreads(); }
    if (tid == 0) atomicAdd(&g_acc[0], (double)red[0]);
    __syncthreads();
    red[tid] = sM; __syncthreads();
    for (int s = 128; s; s >>= 1) { if (tid < s) red[tid] += red[tid + s]; __syncthreads(); }
    if (tid == 0) atomicAdd(&g_acc[1], (double)red[0]);
}

// ---------------------------------------------------------------------------
// GEMM 1 (fp16): Zp[t] = X[t] (B x D) @ F_enc^T (H x D)^T.
// Epilogue: fp16 Zp into the k_zt A layout (flip baked in) + fp32 Zlast @ t=20.
// ---------------------------------------------------------------------------
__global__ void __launch_bounds__(256) k_zp_mma() {
    extern __shared__ char smem[];
    const int tid = threadIdx.x;
    const int lane = tid & 31, warp = tid >> 5;
    const int wm = warp & 1, wn = warp >> 1;
    const int t = blockIdx.z;
    const int m0 = blockIdx.y * 128, n0 = blockIdx.x * 128;

    float acc[4][4][4] = {};
    mma_mainloop_f16<DD>(g_X16 + ((size_t)t * BB + m0) * DD, DD,
                         g_Fe16 + (size_t)n0 * DD, DD,
                         smem, acc);

    const int layer = (t < TAUV) ? (TAUV - 1 - t) : TAUV;
    const int mb = m0 + wm * 64 + (lane >> 2);
    const int nb = n0 + wn * 32 + (lane & 3) * 2;
#pragma unroll
    for (int mi = 0; mi < 4; mi++)
#pragma unroll
        for (int ni = 0; ni < 4; ni++)
#pragma unroll
            for (int half = 0; half < 2; half++) {
                const int m = mb + mi * 16 + half * 8;
                const int n = nb + ni * 8;
                const float f0 = acc[mi][ni][half * 2];
                const float f1 = acc[mi][ni][half * 2 + 1];
                const size_t o = (size_t)m * KTOT + (size_t)layer * HH + n;
                *(__half2*)(g_A16 + o) = __floats2half2_rn(f0, f1);
                if (t == TAUV)
                    *(float2*)(g_Zlast + (size_t)m * HH + n) = make_float2(f0, f1);
            }
}

// ---------------------------------------------------------------------------
// GEMM 2 (fp16, split-K x2): Zt partial over K half blockIdx.z.
// 256 CTAs -> 2 co-resident per SM on most SMs, latency cross-hidden.
// ---------------------------------------------------------------------------
__global__ void __launch_bounds__(256) k_zt_f16() {
    extern __shared__ char smem[];
    const int tid = threadIdx.x;
    const int lane = tid & 31, warp = tid >> 5;
    const int wm = warp & 1, wn = warp >> 1;
    const int m0 = blockIdx.y * 128, n0 = blockIdx.x * 128;
    const int kz = blockIdx.z;

    float acc[4][4][4] = {};
    mma_mainloop_f16<KHALF>(g_A16 + (size_t)m0 * KTOT + (size_t)kz * KHALF, KTOT,
                            g_B16 + (size_t)n0 * KTOT + (size_t)kz * KHALF, KTOT,
                            smem, acc);

    float* out = kz ? g_Zt1 : g_Zt0;
    const int mb = m0 + wm * 64 + (lane >> 2);
    const int nb = n0 + wn * 32 + (lane & 3) * 2;
#pragma unroll
    for (int mi = 0; mi < 4; mi++)
#pragma unroll
        for (int ni = 0; ni < 4; ni++)
#pragma unroll
            for (int half = 0; half < 2; half++) {
                const int m = mb + mi * 16 + half * 8;
                const int n = nb + ni * 8;
                *(float2*)(out + (size_t)m * HH + n) =
                    make_float2(acc[mi][ni][half * 2], acc[mi][ni][half * 2 + 1]);
            }
}

// ---------------------------------------------------------------------------
// GEMM 3 (fp16, fused SSE): recons = Zp[20] (B x H) @ F_dec^T (D x H)^T,
// compared against X20 in fp32; only the SSE leaves the kernel.
// ---------------------------------------------------------------------------
__global__ void __launch_bounds__(256) k_recons_f16() {
    extern __shared__ char smem[];
    const int tid = threadIdx.x;
    const int lane = tid & 31, warp = tid >> 5;
    const int wm = warp & 1, wn = warp >> 1;
    const int m0 = blockIdx.y * 128, n0 = blockIdx.x * 128;
    __shared__ float red[256];

    float acc[4][4][4] = {};
    mma_mainloop_f16<HH>(g_A16 + (size_t)m0 * KTOT + (size_t)TAUV * HH, KTOT,
                         g_Fd16 + (size_t)n0 * HH, HH,
                         smem, acc);

    const int mb = m0 + wm * 64 + (lane >> 2);
    const int nb = n0 + wn * 32 + (lane & 3) * 2;
    float sse = 0.f;
#pragma unroll
    for (int mi = 0; mi < 4; mi++)
#pragma unroll
        for (int ni = 0; ni < 4; ni++)
#pragma unroll
            for (int half = 0; half < 2; half++) {
                const int m = mb + mi * 16 + half * 8;
                const int n = nb + ni * 8;
                const float2 x = *(const float2*)(g_X20 + (size_t)m * DD + n);
                const float d0 = acc[mi][ni][half * 2] - x.x;
                const float d1 = acc[mi][ni][half * 2 + 1] - x.y;
                sse += d0 * d0 + d1 * d1;
            }
    red[tid] = sse; __syncthreads();
    for (int s = 128; s; s >>= 1) { if (tid < s) red[tid] += red[tid + s]; __syncthreads(); }
    if (tid == 0) atomicAdd(&g_acc[2], (double)red[0]);
}

// ---------------------------------------------------------------------------
// Per-row exact top-100 via 8-bit radix select on |Zt|, then masked losses.
// Zt row = g_Zt0 + g_Zt1 (split-K partials, exact fp32 add).
// ---------------------------------------------------------------------------
__global__ void __launch_bounds__(256) k_topk() {
    __shared__ float    zrow[HH];
    __shared__ unsigned hist[256];
    __shared__ unsigned s_prefix;
    __shared__ int      s_k;
    __shared__ float    red[256];

    const int b = blockIdx.x, tid = threadIdx.x;
    const float* zt0 = g_Zt0 + (size_t)b * HH;
    const float* zt1 = g_Zt1 + (size_t)b * HH;
    const float* zl  = g_Zlast + (size_t)b * HH;

    for (int i = tid; i < HH; i += 256) zrow[i] = zt0[i] + zt1[i];
    __syncthreads();

    unsigned prefix = 0u;
    int kneed = KTOP;
    for (int shift = 24; shift >= 0; shift -= 8) {
        hist[tid] = 0u;
        __syncthreads();
        const unsigned hm = (shift == 24) ? 0u : (0xFFFFFFFFu << (shift + 8));
        for (int i = tid; i < HH; i += 256) {
            const unsigned bits = __float_as_uint(fabsf(zrow[i]));
            if ((bits & hm) == prefix) atomicAdd(&hist[(bits >> shift) & 255u], 1u);
        }
        __syncthreads();
        if (tid == 0) {
            int acc = 0;
            for (int bb = 255; bb >= 0; bb--) {
                acc += (int)hist[bb];
                if (acc >= kneed) {
                    s_prefix = prefix | ((unsigned)bb << shift);
                    s_k = kneed - (acc - (int)hist[bb]);
                    break;
                }
            }
        }
        __syncthreads();
        prefix = s_prefix;
        kneed = s_k;
        __syncthreads();
    }
    const unsigned T = prefix;

    // count exact-threshold elements; skip serial tie repair when unambiguous
    int cnt = 0;
    for (int i = tid; i < HH; i += 256)
        if (__float_as_uint(fabsf(zrow[i])) == T) cnt++;
    red[tid] = (float)cnt; __syncthreads();
    for (int s = 128; s; s >>= 1) { if (tid < s) red[tid] += red[tid + s]; __syncthreads(); }
    const int cntT = (int)red[0];
    __syncthreads();
    if (cntT != kneed && tid == 0) {
        int r = kneed;
        for (int i = 0; i < HH; i++) {
            if (__float_as_uint(fabsf(zrow[i])) == T) {
                if (r > 0) r--; else zrow[i] = 0.f;
            }
        }
    }
    __syncthreads();

    float sse = 0.f, sab = 0.f, saz = 0.f;
    for (int i = tid; i < HH; i += 256) {
        const float z  = zrow[i];
        const float zm = (__float_as_uint(fabsf(z)) >= T) ? z : 0.f;
        const float zv = zl[i];
        const float d  = zm - zv;
        sse += d * d;
        sab += fabsf(d);
        saz += fabsf(zm);
    }
    red[tid] = sse; __syncthreads();
    for (int s = 128; s; s >>= 1) { if (tid < s) red[tid] += red[tid + s]; __syncthreads(); }
    if (tid == 0) atomicAdd(&g_acc[3], (double)red[0]);
    __syncthreads();
    red[tid] = sab; __syncthreads();
    for (int s = 128; s; s >>= 1) { if (tid < s) red[tid] += red[tid + s]; __syncthreads(); }
    if (tid == 0) atomicAdd(&g_acc[4], (double)red[0]);
    __syncthreads();
    red[tid] = saz; __syncthreads();
    for (int s = 128; s; s >>= 1) { if (tid < s) red[tid] += red[tid + s]; __syncthreads(); }
    if (tid == 0) atomicAdd(&g_acc[5], (double)red[0]);
}

// ---------------------------------------------------------------------------
__global__ void k_final(float* __restrict__ out) {
    if (threadIdx.x == 0 && blockIdx.x == 0) {
        out[0] = (float)(g_acc[2] / ((double)BB * DD));
        out[1] = (float)(g_acc[3] / ((double)BB * HH));
        out[2] = (float)(g_acc[4] / ((double)BB * HH));
        out[3] = (float)(g_acc[0] / ((double)HH * HH));
        out[4] = (float)(g_acc[1] / ((double)HH * HH));
        out[5] = (float)(g_acc[5] / ((double)BB * HH));
    }
}

// ---------------------------------------------------------------------------
extern "C" void kernel_launch(void* const* d_in, const int* in_sizes, int n_in,
                              void* d_out, int out_size) {
    (void)in_sizes; (void)n_in; (void)out_size;
    const float* Xp  = (const float*)d_in[0];
    const float* Fe  = (const float*)d_in[1];
    const float* Fd  = (const float*)d_in[2];
    const float* Bsw = (const float*)d_in[3];
    const float* Mw  = (const float*)d_in[4];
    float* out = (float*)d_out;

    cudaFuncSetAttribute(k_zp_mma,     cudaFuncAttributeMaxDynamicSharedMemorySize, SMEM_MMA);
    cudaFuncSetAttribute(k_zt_f16,     cudaFuncAttributeMaxDynamicSharedMemorySize, SMEM_MMA);
    cudaFuncSetAttribute(k_recons_f16, cudaFuncAttributeMaxDynamicSharedMemorySize, SMEM_MMA);

    k_init<<<1, 32>>>();
    k_conv_x<<<(BB * DD + 255) / 256, 256>>>(Xp);
    k_conv_fe<<<dim3(DD / 32, HH / 32), dim3(32, 8)>>>(Fe);
    k_conv_fd<<<dim3(HH / 32, DD / 32), dim3(32, 8)>>>(Fd);
    k_convB<<<2048, 256>>>(Bsw, Mw);

    k_zp_mma<<<dim3(HH / 128, BB / 128, TT), 256, SMEM_MMA>>>();
    k_zt_f16<<<dim3(HH / 128, BB / 128, 2), 256, SMEM_MMA>>>();
    k_recons_f16<<<dim3(DD / 128, BB / 128), 256, SMEM_MMA>>>();

    k_topk<<<BB, 256>>>();
    k_final<<<1, 32>>>(out);
}

// round 15
// speedup vs baseline: 1.2213x; 1.0320x over previous
#include <cuda_runtime.h>
#include <cuda_fp16.h>
#include <cstdint>
#include <math.h>

// Problem constants
#define BB   512
#define DD   1024
#define HH   4096
#define TT   21
#define TAUV 20
#define KTOP 100
#define KTOT (TT * HH)        // 86016
#define KQ   (KTOT / 4)       // 21504 (k_zt split-K quarter)
#define BK   32
#define SST  40               // smem k-stride in halves (80 B, ldmatrix-friendly)
#define TEN_BYTES (128 * SST * 2)     // 10240 B per tensor per stage
#define STG  (2 * TEN_BYTES)          // A|B per stage = 20480
#define NST  4
#define SMEM_MMA (NST * STG)          // 81920

// ---------------------------------------------------------------------------
// Static device scratch (no allocations allowed)
// ---------------------------------------------------------------------------
__device__ __half g_X16[(size_t)TT * BB * DD];   // X fp16 [t][b][d]
__device__ float  g_X20[(size_t)BB * DD];        // X[:,:,20] fp32 compact
__device__ __half g_Fe16[(size_t)HH * DD];       // F_enc^T fp16 [h][d]
__device__ __half g_Fd16[(size_t)DD * HH];       // F_dec^T fp16 [d][h]
__device__ __half g_A16[(size_t)BB * KTOT];      // Zp fp16 [b][layer*H+h']
__device__ __half g_B16[(size_t)HH * KTOT];      // Bs/trilM fp16 [h][layer*H+d]
__device__ float g_Zlast[(size_t)BB * HH];       // fp32 Z_last (from k_zp t=20)
__device__ float g_ZtP[4][(size_t)BB * HH];      // Zt split-K partials
__device__ float g_RecP[4][(size_t)BB * DD];     // recons split-K partials
// 0=sum|Bs| 1=sum|trilM| 2=sseX 3=sseZ 4=sumAbsE 5=sum|Zt|
__device__ double g_acc[8];

// ---------------------------------------------------------------------------
// PTX helpers (base-target only: cp.async / ldmatrix / mma.sync)
// ---------------------------------------------------------------------------
__device__ __forceinline__ uint32_t smem_u32(const void* p) {
    uint32_t a;
    asm("{ .reg .u64 t; cvta.to.shared.u64 t, %1; cvt.u32.u64 %0, t; }"
        : "=r"(a) : "l"(p));
    return a;
}
__device__ __forceinline__ void cp_async16(uint32_t saddr, const void* gaddr) {
    asm volatile("cp.async.cg.shared.global [%0], [%1], 16;"
                 :: "r"(saddr), "l"(gaddr) : "memory");
}
__device__ __forceinline__ void cp_commit() {
    asm volatile("cp.async.commit_group;" ::: "memory");
}
__device__ __forceinline__ void cp_wait2() {
    asm volatile("cp.async.wait_group 2;" ::: "memory");
}
__device__ __forceinline__ void cp_wait1() {
    asm volatile("cp.async.wait_group 1;" ::: "memory");
}
__device__ __forceinline__ void cp_wait0() {
    asm volatile("cp.async.wait_group 0;" ::: "memory");
}
__device__ __forceinline__ void ldsm_x4(uint32_t* r, uint32_t addr) {
    asm volatile("ldmatrix.sync.aligned.m8n8.x4.shared.b16 {%0,%1,%2,%3}, [%4];"
                 : "=r"(r[0]), "=r"(r[1]), "=r"(r[2]), "=r"(r[3]) : "r"(addr));
}
__device__ __forceinline__ void mma_f16(float* c, const uint32_t* a, const uint32_t* b) {
    asm volatile(
        "mma.sync.aligned.m16n8k16.row.col.f32.f16.f16.f32 "
        "{%0,%1,%2,%3}, {%4,%5,%6,%7}, {%8,%9}, {%0,%1,%2,%3};"
        : "+f"(c[0]), "+f"(c[1]), "+f"(c[2]), "+f"(c[3])
        : "r"(a[0]), "r"(a[1]), "r"(a[2]), "r"(a[3]), "r"(b[0]), "r"(b[1]));
}

// ---------------------------------------------------------------------------
// fp16 1-term mainloop: acc += A*B over K = KT (per-row strides strA/strB).
// CTA 128x128, 8 warps (2m x 4n), warp tile 64x32, BK=32, 4-stage cp.async,
// single __syncthreads per chunk.  [R10 configuration — 80 KB smem]
// ---------------------------------------------------------------------------
template <int KT>
__device__ __forceinline__ void mma_mainloop_f16(
    const __half* __restrict__ A, size_t strA,
    const __half* __restrict__ B, size_t strB,
    char* smem, float acc[4][4][4])
{
    const int tid  = threadIdx.x;
    const int lane = tid & 31, warp = tid >> 5;
    const int wm = warp & 1, wn = warp >> 1;
    const uint32_t sbase = smem_u32(smem);

    const int lrow = tid >> 1;
    const int lk   = (tid & 1) * 16;
    const size_t growA = (size_t)lrow * strA + lk;
    const size_t growB = (size_t)lrow * strB + lk;
    constexpr int NKT = KT / BK;

    auto issue = [&](int kt) {
        const int s = kt & (NST - 1);
        const size_t ka = growA + (size_t)kt * BK;
        const size_t kb = growB + (size_t)kt * BK;
        const uint32_t so = sbase + s * STG + (lrow * SST + lk) * 2;
        cp_async16(so,                  A + ka);
        cp_async16(so + 16,             A + ka + 8);
        cp_async16(so + TEN_BYTES,      B + kb);
        cp_async16(so + TEN_BYTES + 16, B + kb + 8);
        cp_commit();
    };

    issue(0); issue(1); issue(2);

    const int arow = lane & 15, akc = (lane >> 4) * 8;
    const int brow = lane & 15, bkc = (lane >> 4) * 8;

    for (int kt = 0; kt < NKT; kt++) {
        if (kt + 2 < NKT)      cp_wait2();
        else if (kt + 1 < NKT) cp_wait1();
        else                   cp_wait0();
        __syncthreads();
        if (kt + 3 < NKT) issue(kt + 3);   // overwrites stage (kt-1)&3: safe post-barrier

        const uint32_t tb = sbase + (kt & (NST - 1)) * STG;
#pragma unroll
        for (int kk = 0; kk < 2; kk++) {
            uint32_t a[4][4], bh[4][2];
#pragma unroll
            for (int mi = 0; mi < 4; mi++)
                ldsm_x4(a[mi], tb + ((wm * 64 + mi * 16 + arow) * SST + kk * 16 + akc) * 2);
#pragma unroll
            for (int p = 0; p < 2; p++) {
                uint32_t r[4];
                ldsm_x4(r, tb + TEN_BYTES +
                        ((wn * 32 + p * 16 + brow) * SST + kk * 16 + bkc) * 2);
                bh[2 * p][0] = r[0];     bh[2 * p][1] = r[2];
                bh[2 * p + 1][0] = r[1]; bh[2 * p + 1][1] = r[3];
            }
#pragma unroll
            for (int mi = 0; mi < 4; mi++)
#pragma unroll
                for (int ni = 0; ni < 4; ni++)
                    mma_f16(acc[mi][ni], a[mi], bh[ni]);
        }
    }
    __syncthreads();
}

// ---------------------------------------------------------------------------
__global__ void k_init() {
    if (threadIdx.x < 8) g_acc[threadIdx.x] = 0.0;
}

// Xp (B,D,T) t-fastest -> fp16 [t][b][d] + fp32 X20 [b][d]
__global__ void k_conv_x(const float* __restrict__ Xp) {
    int idx = blockIdx.x * blockDim.x + threadIdx.x;
    if (idx >= BB * DD) return;
    const float* s = Xp + (size_t)idx * TT;
#pragma unroll
    for (int t = 0; t < TT; t++) {
        const float v = s[t];
        g_X16[(size_t)t * BB * DD + idx] = __float2half_rn(v);
        if (t == TAUV) g_X20[idx] = v;
    }
}

// F_enc (D,H) -> transposed fp16 [h][d]
__global__ void k_conv_fe(const float* __restrict__ Fe) {
    __shared__ float tile[32][33];
    const int d0 = blockIdx.x * 32, h0 = blockIdx.y * 32;
    for (int r = threadIdx.y; r < 32; r += 8)
        tile[r][threadIdx.x] = Fe[(size_t)(d0 + r) * HH + h0 + threadIdx.x];
    __syncthreads();
    for (int r = threadIdx.y; r < 32; r += 8)
        g_Fe16[(size_t)(h0 + r) * DD + d0 + threadIdx.x] =
            __float2half_rn(tile[threadIdx.x][r]);
}

// F_dec (H,D) -> transposed fp16 [d][h]
__global__ void k_conv_fd(const float* __restrict__ Fd) {
    __shared__ float tile[32][33];
    const int h0 = blockIdx.x * 32, d0 = blockIdx.y * 32;
    for (int r = threadIdx.y; r < 32; r += 8)
        tile[r][threadIdx.x] = Fd[(size_t)(h0 + r) * DD + d0 + threadIdx.x];
    __syncthreads();
    for (int r = threadIdx.y; r < 32; r += 8)
        g_Fd16[(size_t)(d0 + r) * HH + h0 + threadIdx.x] =
            __float2half_rn(tile[threadIdx.x][r]);
}

// Bs (20,H,H) + tril(M,1) -> fp16 [h][layer*H+d], fused |Bs| / |M| sums
__global__ void __launch_bounds__(256) k_convB(const float* __restrict__ Bsw,
                                               const float* __restrict__ Mw) {
    __shared__ float red[256];
    const size_t total = (size_t)TT * HH * (HH / 4);   // float4 units
    float sBs = 0.f, sM = 0.f;
    for (size_t u = blockIdx.x * 256 + threadIdx.x; u < total;
         u += (size_t)gridDim.x * 256) {
        const int d4 = (int)(u & 1023);
        const int h  = (int)((u >> 10) & 4095);
        const int l  = (int)(u >> 22);
        float4 v;
        if (l < TAUV) {
            v = __ldcs((const float4*)(Bsw + (((size_t)l * HH + h) * HH + d4 * 4)));
            sBs += fabsf(v.x) + fabsf(v.y) + fabsf(v.z) + fabsf(v.w);
        } else {
            v = *(const float4*)(Mw + ((size_t)h * HH + d4 * 4));
            float* e = (float*)&v;
#pragma unroll
            for (int j = 0; j < 4; j++)
                if (d4 * 4 + j > h + 1) e[j] = 0.f;
            sM += fabsf(v.x) + fabsf(v.y) + fabsf(v.z) + fabsf(v.w);
        }
        union { __half2 b; uint32_t u; } p0, p1;
        p0.b = __floats2half2_rn(v.x, v.y);
        p1.b = __floats2half2_rn(v.z, v.w);
        *(uint2*)(g_B16 + (size_t)h * KTOT + (size_t)l * HH + d4 * 4) =
            make_uint2(p0.u, p1.u);
    }
    const int tid = threadIdx.x;
    red[tid] = sBs; __syncthreads();
    for (int s = 128; s; s >>= 1) { if (tid < s) red[tid] += red[tid + s]; __syncthreads(); }
    if (tid == 0) atomicAdd(&g_acc[0], (double)red[0]);
    __syncthreads();
    red[tid] = sM; __syncthreads();
    for (int s = 128; s; s >>= 1) { if (tid < s) red[tid] += red[tid + s]; __syncthreads(); }
    if (tid == 0) atomicAdd(&g_acc[1], (double)red[0]);
}

// ---------------------------------------------------------------------------
// GEMM 1 (fp16): Zp[t] = X[t] (B x D) @ F_enc^T (H x D)^T.
// Epilogue: fp16 Zp into the k_zt A layout (flip baked in) + fp32 Zlast @ t=20.
// ---------------------------------------------------------------------------
__global__ void __launch_bounds__(256) k_zp_mma() {
    extern __shared__ char smem[];
    const int tid = threadIdx.x;
    const int lane = tid & 31, warp = tid >> 5;
    const int wm = warp & 1, wn = warp >> 1;
    const int t = blockIdx.z;
    const int m0 = blockIdx.y * 128, n0 = blockIdx.x * 128;

    float acc[4][4][4] = {};
    mma_mainloop_f16<DD>(g_X16 + ((size_t)t * BB + m0) * DD, DD,
                         g_Fe16 + (size_t)n0 * DD, DD,
                         smem, acc);

    const int layer = (t < TAUV) ? (TAUV - 1 - t) : TAUV;
    const int mb = m0 + wm * 64 + (lane >> 2);
    const int nb = n0 + wn * 32 + (lane & 3) * 2;
#pragma unroll
    for (int mi = 0; mi < 4; mi++)
#pragma unroll
        for (int ni = 0; ni < 4; ni++)
#pragma unroll
            for (int half = 0; half < 2; half++) {
                const int m = mb + mi * 16 + half * 8;
                const int n = nb + ni * 8;
                const float f0 = acc[mi][ni][half * 2];
                const float f1 = acc[mi][ni][half * 2 + 1];
                const size_t o = (size_t)m * KTOT + (size_t)layer * HH + n;
                *(__half2*)(g_A16 + o) = __floats2half2_rn(f0, f1);
                if (t == TAUV)
                    *(float2*)(g_Zlast + (size_t)m * HH + n) = make_float2(f0, f1);
            }
}

// ---------------------------------------------------------------------------
// GEMM 2 (fp16, split-K x4): Zt partial over K quarter blockIdx.z.
// 512 CTAs -> sustained 2-CTA co-residency with small tail.
// ---------------------------------------------------------------------------
__global__ void __launch_bounds__(256) k_zt_f16() {
    extern __shared__ char smem[];
    const int tid = threadIdx.x;
    const int lane = tid & 31, warp = tid >> 5;
    const int wm = warp & 1, wn = warp >> 1;
    const int m0 = blockIdx.y * 128, n0 = blockIdx.x * 128;
    const int kz = blockIdx.z;

    float acc[4][4][4] = {};
    mma_mainloop_f16<KQ>(g_A16 + (size_t)m0 * KTOT + (size_t)kz * KQ, KTOT,
                         g_B16 + (size_t)n0 * KTOT + (size_t)kz * KQ, KTOT,
                         smem, acc);

    float* out = g_ZtP[kz];
    const int mb = m0 + wm * 64 + (lane >> 2);
    const int nb = n0 + wn * 32 + (lane & 3) * 2;
#pragma unroll
    for (int mi = 0; mi < 4; mi++)
#pragma unroll
        for (int ni = 0; ni < 4; ni++)
#pragma unroll
            for (int half = 0; half < 2; half++) {
                const int m = mb + mi * 16 + half * 8;
                const int n = nb + ni * 8;
                *(float2*)(out + (size_t)m * HH + n) =
                    make_float2(acc[mi][ni][half * 2], acc[mi][ni][half * 2 + 1]);
            }
}

// ---------------------------------------------------------------------------
// GEMM 3 (fp16, split-K x4): recons partial = Zp[20] slice @ F_dec^T slice.
// 128 CTAs. Partials written fp32; k_sse does the sum + SSE.
// ---------------------------------------------------------------------------
__global__ void __launch_bounds__(256) k_recons_f16() {
    extern __shared__ char smem[];
    const int tid = threadIdx.x;
    const int lane = tid & 31, warp = tid >> 5;
    const int wm = warp & 1, wn = warp >> 1;
    const int m0 = blockIdx.y * 128, n0 = blockIdx.x * 128;
    const int kz = blockIdx.z;

    float acc[4][4][4] = {};
    mma_mainloop_f16<HH / 4>(
        g_A16 + (size_t)m0 * KTOT + (size_t)TAUV * HH + (size_t)kz * (HH / 4), KTOT,
        g_Fd16 + (size_t)n0 * HH + (size_t)kz * (HH / 4), HH,
        smem, acc);

    float* out = g_RecP[kz];
    const int mb = m0 + wm * 64 + (lane >> 2);
    const int nb = n0 + wn * 32 + (lane & 3) * 2;
#pragma unroll
    for (int mi = 0; mi < 4; mi++)
#pragma unroll
        for (int ni = 0; ni < 4; ni++)
#pragma unroll
            for (int half = 0; half < 2; half++) {
                const int m = mb + mi * 16 + half * 8;
                const int n = nb + ni * 8;
                *(float2*)(out + (size_t)m * DD + n) =
                    make_float2(acc[mi][ni][half * 2], acc[mi][ni][half * 2 + 1]);
            }
}

// Sum recons partials, SSE vs X20 -> g_acc[2].
__global__ void __launch_bounds__(256) k_sse() {
    __shared__ float red[256];
    const int tid = threadIdx.x;
    float sse = 0.f;
    for (size_t i = blockIdx.x * 256 + tid; i < (size_t)BB * DD;
         i += (size_t)gridDim.x * 256) {
        const float r = g_RecP[0][i] + g_RecP[1][i] + g_RecP[2][i] + g_RecP[3][i];
        const float d = r - g_X20[i];
        sse += d * d;
    }
    red[tid] = sse; __syncthreads();
    for (int s = 128; s; s >>= 1) { if (tid < s) red[tid] += red[tid + s]; __syncthreads(); }
    if (tid == 0) atomicAdd(&g_acc[2], (double)red[0]);
}

// ---------------------------------------------------------------------------
// Per-row exact top-100 via 8-bit radix select on |Zt|, then masked losses.
// Zt row = sum of 4 split-K partials (exact fp32 adds).
// ---------------------------------------------------------------------------
__global__ void __launch_bounds__(256) k_topk() {
    __shared__ float    zrow[HH];
    __shared__ unsigned hist[256];
    __shared__ unsigned s_prefix;
    __shared__ int      s_k;
    __shared__ float    red[256];

    const int b = blockIdx.x, tid = threadIdx.x;
    const size_t off = (size_t)b * HH;
    const float* zl = g_Zlast + off;

    for (int i = tid; i < HH; i += 256)
        zrow[i] = (g_ZtP[0][off + i] + g_ZtP[1][off + i])
                + (g_ZtP[2][off + i] + g_ZtP[3][off + i]);
    __syncthreads();

    unsigned prefix = 0u;
    int kneed = KTOP;
    for (int shift = 24; shift >= 0; shift -= 8) {
        hist[tid] = 0u;
        __syncthreads();
        const unsigned hm = (shift == 24) ? 0u : (0xFFFFFFFFu << (shift + 8));
        for (int i = tid; i < HH; i += 256) {
            const unsigned bits = __float_as_uint(fabsf(zrow[i]));
            if ((bits & hm) == prefix) atomicAdd(&hist[(bits >> shift) & 255u], 1u);
        }
        __syncthreads();
        if (tid == 0) {
            int acc = 0;
            for (int bb = 255; bb >= 0; bb--) {
                acc += (int)hist[bb];
                if (acc >= kneed) {
                    s_prefix = prefix | ((unsigned)bb << shift);
                    s_k = kneed - (acc - (int)hist[bb]);
                    break;
                }
            }
        }
        __syncthreads();
        prefix = s_prefix;
        kneed = s_k;
        __syncthreads();
    }
    const unsigned T = prefix;

    // count exact-threshold elements; skip serial tie repair when unambiguous
    int cnt = 0;
    for (int i = tid; i < HH; i += 256)
        if (__float_as_uint(fabsf(zrow[i])) == T) cnt++;
    red[tid] = (float)cnt; __syncthreads();
    for (int s = 128; s; s >>= 1) { if (tid < s) red[tid] += red[tid + s]; __syncthreads(); }
    const int cntT = (int)red[0];
    __syncthreads();
    if (cntT != kneed && tid == 0) {
        int r = kneed;
        for (int i = 0; i < HH; i++) {
            if (__float_as_uint(fabsf(zrow[i])) == T) {
                if (r > 0) r--; else zrow[i] = 0.f;
            }
        }
    }
    __syncthreads();

    float sse = 0.f, sab = 0.f, saz = 0.f;
    for (int i = tid; i < HH; i += 256) {
        const float z  = zrow[i];
        const float zm = (__float_as_uint(fabsf(z)) >= T) ? z : 0.f;
        const float zv = zl[i];
        const float d  = zm - zv;
        sse += d * d;
        sab += fabsf(d);
        saz += fabsf(zm);
    }
    red[tid] = sse; __syncthreads();
    for (int s = 128; s; s >>= 1) { if (tid < s) red[tid] += red[tid + s]; __syncthreads(); }
    if (tid == 0) atomicAdd(&g_acc[3], (double)red[0]);
    __syncthreads();
    red[tid] = sab; __syncthreads();
    for (int s = 128; s; s >>= 1) { if (tid < s) red[tid] += red[tid + s]; __syncthreads(); }
    if (tid == 0) atomicAdd(&g_acc[4], (double)red[0]);
    __syncthreads();
    red[tid] = saz; __syncthreads();
    for (int s = 128; s; s >>= 1) { if (tid < s) red[tid] += red[tid + s]; __syncthreads(); }
    if (tid == 0) atomicAdd(&g_acc[5], (double)red[0]);
}

// ---------------------------------------------------------------------------
__global__ void k_final(float* __restrict__ out) {
    if (threadIdx.x == 0 && blockIdx.x == 0) {
        out[0] = (float)(g_acc[2] / ((double)BB * DD));
        out[1] = (float)(g_acc[3] / ((double)BB * HH));
        out[2] = (float)(g_acc[4] / ((double)BB * HH));
        out[3] = (float)(g_acc[0] / ((double)HH * HH));
        out[4] = (float)(g_acc[1] / ((double)HH * HH));
        out[5] = (float)(g_acc[5] / ((double)BB * HH));
    }
}

// ---------------------------------------------------------------------------
extern "C" void kernel_launch(void* const* d_in, const int* in_sizes, int n_in,
                              void* d_out, int out_size) {
    (void)in_sizes; (void)n_in; (void)out_size;
    const float* Xp  = (const float*)d_in[0];
    const float* Fe  = (const float*)d_in[1];
    const float* Fd  = (const float*)d_in[2];
    const float* Bsw = (const float*)d_in[3];
    const float* Mw  = (const float*)d_in[4];
    float* out = (float*)d_out;

    cudaFuncSetAttribute(k_zp_mma,     cudaFuncAttributeMaxDynamicSharedMemorySize, SMEM_MMA);
    cudaFuncSetAttribute(k_zt_f16,     cudaFuncAttributeMaxDynamicSharedMemorySize, SMEM_MMA);
    cudaFuncSetAttribute(k_recons_f16, cudaFuncAttributeMaxDynamicSharedMemorySize, SMEM_MMA);

    k_init<<<1, 32>>>();
    k_conv_x<<<(BB * DD + 255) / 256, 256>>>(Xp);
    k_conv_fe<<<dim3(DD / 32, HH / 32), dim3(32, 8)>>>(Fe);
    k_conv_fd<<<dim3(HH / 32, DD / 32), dim3(32, 8)>>>(Fd);
    k_convB<<<2048, 256>>>(Bsw, Mw);

    k_zp_mma<<<dim3(HH / 128, BB / 128, TT), 256, SMEM_MMA>>>();
    k_zt_f16<<<dim3(HH / 128, BB / 128, 4), 256, SMEM_MMA>>>();
    k_recons_f16<<<dim3(DD / 128, BB / 128, 4), 256, SMEM_MMA>>>();

    k_sse<<<1024, 256>>>();
    k_topk<<<BB, 256>>>();
    k_final<<<1, 32>>>(out);
}

// round 16
// speedup vs baseline: 1.2281x; 1.0055x over previous
#include <cuda_runtime.h>
#include <cuda_fp16.h>
#include <cstdint>
#include <math.h>

// Problem constants
#define BB   512
#define DD   1024
#define HH   4096
#define TT   21
#define TAUV 20
#define KTOP 100
#define KTOT (TT * HH)        // 86016
#define KQ   (KTOT / 4)       // 21504 (k_zt split-K quarter)
#define BK   32
#define SST  40               // smem k-stride in halves (80 B, ldmatrix-friendly)
#define TEN_BYTES (128 * SST * 2)     // 10240 B per tensor per stage
#define STG  (2 * TEN_BYTES)          // A|B per stage = 20480
#define NST  4
#define SMEM_MMA (NST * STG)          // 81920

// ---------------------------------------------------------------------------
// Static device scratch (no allocations allowed)
// ---------------------------------------------------------------------------
__device__ __half g_X16[(size_t)TT * BB * DD];   // X fp16 [t][b][d]
__device__ float  g_X20[(size_t)BB * DD];        // X[:,:,20] fp32 compact
__device__ __half g_Fe16[(size_t)HH * DD];       // F_enc^T fp16 [h][d]
__device__ __half g_Fd16[(size_t)DD * HH];       // F_dec^T fp16 [d][h]
__device__ __half g_A16[(size_t)BB * KTOT];      // Zp fp16 [b][layer*H+h']
__device__ __half g_B16[(size_t)HH * KTOT];      // Bs/trilM fp16 [h][layer*H+d]
__device__ float g_Zlast[(size_t)BB * HH];       // fp32 Z_last (from k_zp t=20)
__device__ float g_ZtP[4][(size_t)BB * HH];      // Zt split-K partials
__device__ float g_RecP[4][(size_t)BB * DD];     // recons split-K partials
// 0=sum|Bs| 1=sum|trilM| 2=sseX 3=sseZ 4=sumAbsE 5=sum|Zt|
__device__ double g_acc[8];

// ---------------------------------------------------------------------------
// PTX helpers (base-target only: cp.async / ldmatrix / mma.sync)
// ---------------------------------------------------------------------------
__device__ __forceinline__ uint32_t smem_u32(const void* p) {
    uint32_t a;
    asm("{ .reg .u64 t; cvta.to.shared.u64 t, %1; cvt.u32.u64 %0, t; }"
        : "=r"(a) : "l"(p));
    return a;
}
__device__ __forceinline__ void cp_async16(uint32_t saddr, const void* gaddr) {
    asm volatile("cp.async.cg.shared.global [%0], [%1], 16;"
                 :: "r"(saddr), "l"(gaddr) : "memory");
}
__device__ __forceinline__ void cp_commit() {
    asm volatile("cp.async.commit_group;" ::: "memory");
}
__device__ __forceinline__ void cp_wait2() {
    asm volatile("cp.async.wait_group 2;" ::: "memory");
}
__device__ __forceinline__ void cp_wait1() {
    asm volatile("cp.async.wait_group 1;" ::: "memory");
}
__device__ __forceinline__ void cp_wait0() {
    asm volatile("cp.async.wait_group 0;" ::: "memory");
}
__device__ __forceinline__ void ldsm_x4(uint32_t* r, uint32_t addr) {
    asm volatile("ldmatrix.sync.aligned.m8n8.x4.shared.b16 {%0,%1,%2,%3}, [%4];"
                 : "=r"(r[0]), "=r"(r[1]), "=r"(r[2]), "=r"(r[3]) : "r"(addr));
}
__device__ __forceinline__ void mma_f16(float* c, const uint32_t* a, const uint32_t* b) {
    asm volatile(
        "mma.sync.aligned.m16n8k16.row.col.f32.f16.f16.f32 "
        "{%0,%1,%2,%3}, {%4,%5,%6,%7}, {%8,%9}, {%0,%1,%2,%3};"
        : "+f"(c[0]), "+f"(c[1]), "+f"(c[2]), "+f"(c[3])
        : "r"(a[0]), "r"(a[1]), "r"(a[2]), "r"(a[3]), "r"(b[0]), "r"(b[1]));
}

// ---------------------------------------------------------------------------
// fp16 1-term mainloop: acc += A*B over K = KT (per-row strides strA/strB).
// CTA 128x128, 8 warps (2m x 4n), warp tile 64x32, BK=32, 4-stage cp.async,
// single __syncthreads per chunk.  [R10 configuration — 80 KB smem]
// ---------------------------------------------------------------------------
template <int KT>
__device__ __forceinline__ void mma_mainloop_f16(
    const __half* __restrict__ A, size_t strA,
    const __half* __restrict__ B, size_t strB,
    char* smem, float acc[4][4][4])
{
    const int tid  = threadIdx.x;
    const int lane = tid & 31, warp = tid >> 5;
    const int wm = warp & 1, wn = warp >> 1;
    const uint32_t sbase = smem_u32(smem);

    const int lrow = tid >> 1;
    const int lk   = (tid & 1) * 16;
    const size_t growA = (size_t)lrow * strA + lk;
    const size_t growB = (size_t)lrow * strB + lk;
    constexpr int NKT = KT / BK;

    auto issue = [&](int kt) {
        const int s = kt & (NST - 1);
        const size_t ka = growA + (size_t)kt * BK;
        const size_t kb = growB + (size_t)kt * BK;
        const uint32_t so = sbase + s * STG + (lrow * SST + lk) * 2;
        cp_async16(so,                  A + ka);
        cp_async16(so + 16,             A + ka + 8);
        cp_async16(so + TEN_BYTES,      B + kb);
        cp_async16(so + TEN_BYTES + 16, B + kb + 8);
        cp_commit();
    };

    issue(0); issue(1); issue(2);

    const int arow = lane & 15, akc = (lane >> 4) * 8;
    const int brow = lane & 15, bkc = (lane >> 4) * 8;

    for (int kt = 0; kt < NKT; kt++) {
        if (kt + 2 < NKT)      cp_wait2();
        else if (kt + 1 < NKT) cp_wait1();
        else                   cp_wait0();
        __syncthreads();
        if (kt + 3 < NKT) issue(kt + 3);   // overwrites stage (kt-1)&3: safe post-barrier

        const uint32_t tb = sbase + (kt & (NST - 1)) * STG;
#pragma unroll
        for (int kk = 0; kk < 2; kk++) {
            uint32_t a[4][4], bh[4][2];
#pragma unroll
            for (int mi = 0; mi < 4; mi++)
                ldsm_x4(a[mi], tb + ((wm * 64 + mi * 16 + arow) * SST + kk * 16 + akc) * 2);
#pragma unroll
            for (int p = 0; p < 2; p++) {
                uint32_t r[4];
                ldsm_x4(r, tb + TEN_BYTES +
                        ((wn * 32 + p * 16 + brow) * SST + kk * 16 + bkc) * 2);
                bh[2 * p][0] = r[0];     bh[2 * p][1] = r[2];
                bh[2 * p + 1][0] = r[1]; bh[2 * p + 1][1] = r[3];
            }
#pragma unroll
            for (int mi = 0; mi < 4; mi++)
#pragma unroll
                for (int ni = 0; ni < 4; ni++)
                    mma_f16(acc[mi][ni], a[mi], bh[ni]);
        }
    }
    __syncthreads();
}

// ---------------------------------------------------------------------------
__global__ void k_init() {
    if (threadIdx.x < 8) g_acc[threadIdx.x] = 0.0;
}

// Xp (B,D,T) t-fastest -> fp16 [t][b][d] + fp32 X20 [b][d]
__global__ void k_conv_x(const float* __restrict__ Xp) {
    int idx = blockIdx.x * blockDim.x + threadIdx.x;
    if (idx >= BB * DD) return;
    const float* s = Xp + (size_t)idx * TT;
#pragma unroll
    for (int t = 0; t < TT; t++) {
        const float v = s[t];
        g_X16[(size_t)t * BB * DD + idx] = __float2half_rn(v);
        if (t == TAUV) g_X20[idx] = v;
    }
}

// F_enc (D,H) -> transposed fp16 [h][d]
__global__ void k_conv_fe(const float* __restrict__ Fe) {
    __shared__ float tile[32][33];
    const int d0 = blockIdx.x * 32, h0 = blockIdx.y * 32;
    for (int r = threadIdx.y; r < 32; r += 8)
        tile[r][threadIdx.x] = Fe[(size_t)(d0 + r) * HH + h0 + threadIdx.x];
    __syncthreads();
    for (int r = threadIdx.y; r < 32; r += 8)
        g_Fe16[(size_t)(h0 + r) * DD + d0 + threadIdx.x] =
            __float2half_rn(tile[threadIdx.x][r]);
}

// F_dec (H,D) -> transposed fp16 [d][h]
__global__ void k_conv_fd(const float* __restrict__ Fd) {
    __shared__ float tile[32][33];
    const int h0 = blockIdx.x * 32, d0 = blockIdx.y * 32;
    for (int r = threadIdx.y; r < 32; r += 8)
        tile[r][threadIdx.x] = Fd[(size_t)(h0 + r) * DD + d0 + threadIdx.x];
    __syncthreads();
    for (int r = threadIdx.y; r < 32; r += 8)
        g_Fd16[(size_t)(d0 + r) * HH + h0 + threadIdx.x] =
            __float2half_rn(tile[threadIdx.x][r]);
}

// Bs (20,H,H) + tril(M,1) -> fp16 [h][layer*H+d], fused |Bs| / |M| sums
__global__ void __launch_bounds__(256) k_convB(const float* __restrict__ Bsw,
                                               const float* __restrict__ Mw) {
    __shared__ float red[256];
    const size_t total = (size_t)TT * HH * (HH / 4);   // float4 units
    float sBs = 0.f, sM = 0.f;
    for (size_t u = blockIdx.x * 256 + threadIdx.x; u < total;
         u += (size_t)gridDim.x * 256) {
        const int d4 = (int)(u & 1023);
        const int h  = (int)((u >> 10) & 4095);
        const int l  = (int)(u >> 22);
        float4 v;
        if (l < TAUV) {
            v = __ldcs((const float4*)(Bsw + (((size_t)l * HH + h) * HH + d4 * 4)));
            sBs += fabsf(v.x) + fabsf(v.y) + fabsf(v.z) + fabsf(v.w);
        } else {
            v = *(const float4*)(Mw + ((size_t)h * HH + d4 * 4));
            float* e = (float*)&v;
#pragma unroll
            for (int j = 0; j < 4; j++)
                if (d4 * 4 + j > h + 1) e[j] = 0.f;
            sM += fabsf(v.x) + fabsf(v.y) + fabsf(v.z) + fabsf(v.w);
        }
        union { __half2 b; uint32_t u; } p0, p1;
        p0.b = __floats2half2_rn(v.x, v.y);
        p1.b = __floats2half2_rn(v.z, v.w);
        *(uint2*)(g_B16 + (size_t)h * KTOT + (size_t)l * HH + d4 * 4) =
            make_uint2(p0.u, p1.u);
    }
    const int tid = threadIdx.x;
    red[tid] = sBs; __syncthreads();
    for (int s = 128; s; s >>= 1) { if (tid < s) red[tid] += red[tid + s]; __syncthreads(); }
    if (tid == 0) atomicAdd(&g_acc[0], (double)red[0]);
    __syncthreads();
    red[tid] = sM; __syncthreads();
    for (int s = 128; s; s >>= 1) { if (tid < s) red[tid] += red[tid + s]; __syncthreads(); }
    if (tid == 0) atomicAdd(&g_acc[1], (double)red[0]);
}

// ---------------------------------------------------------------------------
// GEMM 1 (fp16): Zp[t] = X[t] (B x D) @ F_enc^T (H x D)^T.
// Epilogue: fp16 Zp into the k_zt A layout (flip baked in) + fp32 Zlast @ t=20.
// ---------------------------------------------------------------------------
__global__ void __launch_bounds__(256) k_zp_mma() {
    extern __shared__ char smem[];
    const int tid = threadIdx.x;
    const int lane = tid & 31, warp = tid >> 5;
    const int wm = warp & 1, wn = warp >> 1;
    const int t = blockIdx.z;
    const int m0 = blockIdx.y * 128, n0 = blockIdx.x * 128;

    float acc[4][4][4] = {};
    mma_mainloop_f16<DD>(g_X16 + ((size_t)t * BB + m0) * DD, DD,
                         g_Fe16 + (size_t)n0 * DD, DD,
                         smem, acc);

    const int layer = (t < TAUV) ? (TAUV - 1 - t) : TAUV;
    const int mb = m0 + wm * 64 + (lane >> 2);
    const int nb = n0 + wn * 32 + (lane & 3) * 2;
#pragma unroll
    for (int mi = 0; mi < 4; mi++)
#pragma unroll
        for (int ni = 0; ni < 4; ni++)
#pragma unroll
            for (int half = 0; half < 2; half++) {
                const int m = mb + mi * 16 + half * 8;
                const int n = nb + ni * 8;
                const float f0 = acc[mi][ni][half * 2];
                const float f1 = acc[mi][ni][half * 2 + 1];
                const size_t o = (size_t)m * KTOT + (size_t)layer * HH + n;
                *(__half2*)(g_A16 + o) = __floats2half2_rn(f0, f1);
                if (t == TAUV)
                    *(float2*)(g_Zlast + (size_t)m * HH + n) = make_float2(f0, f1);
            }
}

// ---------------------------------------------------------------------------
// GEMM 2 (fp16, split-K x4): Zt partial over K quarter blockIdx.z.
// ---------------------------------------------------------------------------
__global__ void __launch_bounds__(256) k_zt_f16() {
    extern __shared__ char smem[];
    const int tid = threadIdx.x;
    const int lane = tid & 31, warp = tid >> 5;
    const int wm = warp & 1, wn = warp >> 1;
    const int m0 = blockIdx.y * 128, n0 = blockIdx.x * 128;
    const int kz = blockIdx.z;

    float acc[4][4][4] = {};
    mma_mainloop_f16<KQ>(g_A16 + (size_t)m0 * KTOT + (size_t)kz * KQ, KTOT,
                         g_B16 + (size_t)n0 * KTOT + (size_t)kz * KQ, KTOT,
                         smem, acc);

    float* out = g_ZtP[kz];
    const int mb = m0 + wm * 64 + (lane >> 2);
    const int nb = n0 + wn * 32 + (lane & 3) * 2;
#pragma unroll
    for (int mi = 0; mi < 4; mi++)
#pragma unroll
        for (int ni = 0; ni < 4; ni++)
#pragma unroll
            for (int half = 0; half < 2; half++) {
                const int m = mb + mi * 16 + half * 8;
                const int n = nb + ni * 8;
                *(float2*)(out + (size_t)m * HH + n) =
                    make_float2(acc[mi][ni][half * 2], acc[mi][ni][half * 2 + 1]);
            }
}

// ---------------------------------------------------------------------------
// GEMM 3 (fp16, split-K x4): recons partial = Zp[20] slice @ F_dec^T slice.
// ---------------------------------------------------------------------------
__global__ void __launch_bounds__(256) k_recons_f16() {
    extern __shared__ char smem[];
    const int tid = threadIdx.x;
    const int lane = tid & 31, warp = tid >> 5;
    const int wm = warp & 1, wn = warp >> 1;
    const int m0 = blockIdx.y * 128, n0 = blockIdx.x * 128;
    const int kz = blockIdx.z;

    float acc[4][4][4] = {};
    mma_mainloop_f16<HH / 4>(
        g_A16 + (size_t)m0 * KTOT + (size_t)TAUV * HH + (size_t)kz * (HH / 4), KTOT,
        g_Fd16 + (size_t)n0 * HH + (size_t)kz * (HH / 4), HH,
        smem, acc);

    float* out = g_RecP[kz];
    const int mb = m0 + wm * 64 + (lane >> 2);
    const int nb = n0 + wn * 32 + (lane & 3) * 2;
#pragma unroll
    for (int mi = 0; mi < 4; mi++)
#pragma unroll
        for (int ni = 0; ni < 4; ni++)
#pragma unroll
            for (int half = 0; half < 2; half++) {
                const int m = mb + mi * 16 + half * 8;
                const int n = nb + ni * 8;
                *(float2*)(out + (size_t)m * DD + n) =
                    make_float2(acc[mi][ni][half * 2], acc[mi][ni][half * 2 + 1]);
            }
}

// Sum recons partials, SSE vs X20 -> g_acc[2].
__global__ void __launch_bounds__(256) k_sse() {
    __shared__ float red[256];
    const int tid = threadIdx.x;
    float sse = 0.f;
    for (size_t i = blockIdx.x * 256 + tid; i < (size_t)BB * DD;
         i += (size_t)gridDim.x * 256) {
        const float r = g_RecP[0][i] + g_RecP[1][i] + g_RecP[2][i] + g_RecP[3][i];
        const float d = r - g_X20[i];
        sse += d * d;
    }
    red[tid] = sse; __syncthreads();
    for (int s = 128; s; s >>= 1) { if (tid < s) red[tid] += red[tid + s]; __syncthreads(); }
    if (tid == 0) atomicAdd(&g_acc[2], (double)red[0]);
}

// ---------------------------------------------------------------------------
// Per-row exact top-100 via 8-bit radix select on |Zt|, then masked losses.
// ---------------------------------------------------------------------------
__global__ void __launch_bounds__(256) k_topk() {
    __shared__ float    zrow[HH];
    __shared__ unsigned hist[256];
    __shared__ unsigned s_prefix;
    __shared__ int      s_k;
    __shared__ float    red[256];

    const int b = blockIdx.x, tid = threadIdx.x;
    const size_t off = (size_t)b * HH;
    const float* zl = g_Zlast + off;

    for (int i = tid; i < HH; i += 256)
        zrow[i] = (g_ZtP[0][off + i] + g_ZtP[1][off + i])
                + (g_ZtP[2][off + i] + g_ZtP[3][off + i]);
    __syncthreads();

    unsigned prefix = 0u;
    int kneed = KTOP;
    for (int shift = 24; shift >= 0; shift -= 8) {
        hist[tid] = 0u;
        __syncthreads();
        const unsigned hm = (shift == 24) ? 0u : (0xFFFFFFFFu << (shift + 8));
        for (int i = tid; i < HH; i += 256) {
            const unsigned bits = __float_as_uint(fabsf(zrow[i]));
            if ((bits & hm) == prefix) atomicAdd(&hist[(bits >> shift) & 255u], 1u);
        }
        __syncthreads();
        if (tid == 0) {
            int acc = 0;
            for (int bb = 255; bb >= 0; bb--) {
                acc += (int)hist[bb];
                if (acc >= kneed) {
                    s_prefix = prefix | ((unsigned)bb << shift);
                    s_k = kneed - (acc - (int)hist[bb]);
                    break;
                }
            }
        }
        __syncthreads();
        prefix = s_prefix;
        kneed = s_k;
        __syncthreads();
    }
    const unsigned T = prefix;

    // count exact-threshold elements; skip serial tie repair when unambiguous
    int cnt = 0;
    for (int i = tid; i < HH; i += 256)
        if (__float_as_uint(fabsf(zrow[i])) == T) cnt++;
    red[tid] = (float)cnt; __syncthreads();
    for (int s = 128; s; s >>= 1) { if (tid < s) red[tid] += red[tid + s]; __syncthreads(); }
    const int cntT = (int)red[0];
    __syncthreads();
    if (cntT != kneed && tid == 0) {
        int r = kneed;
        for (int i = 0; i < HH; i++) {
            if (__float_as_uint(fabsf(zrow[i])) == T) {
                if (r > 0) r--; else zrow[i] = 0.f;
            }
        }
    }
    __syncthreads();

    float sse = 0.f, sab = 0.f, saz = 0.f;
    for (int i = tid; i < HH; i += 256) {
        const float z  = zrow[i];
        const float zm = (__float_as_uint(fabsf(z)) >= T) ? z : 0.f;
        const float zv = zl[i];
        const float d  = zm - zv;
        sse += d * d;
        sab += fabsf(d);
        saz += fabsf(zm);
    }
    red[tid] = sse; __syncthreads();
    for (int s = 128; s; s >>= 1) { if (tid < s) red[tid] += red[tid + s]; __syncthreads(); }
    if (tid == 0) atomicAdd(&g_acc[3], (double)red[0]);
    __syncthreads();
    red[tid] = sab; __syncthreads();
    for (int s = 128; s; s >>= 1) { if (tid < s) red[tid] += red[tid + s]; __syncthreads(); }
    if (tid == 0) atomicAdd(&g_acc[4], (double)red[0]);
    __syncthreads();
    red[tid] = saz; __syncthreads();
    for (int s = 128; s; s >>= 1) { if (tid < s) red[tid] += red[tid + s]; __syncthreads(); }
    if (tid == 0) atomicAdd(&g_acc[5], (double)red[0]);
}

// ---------------------------------------------------------------------------
__global__ void k_final(float* __restrict__ out) {
    if (threadIdx.x == 0 && blockIdx.x == 0) {
        out[0] = (float)(g_acc[2] / ((double)BB * DD));
        out[1] = (float)(g_acc[3] / ((double)BB * HH));
        out[2] = (float)(g_acc[4] / ((double)BB * HH));
        out[3] = (float)(g_acc[0] / ((double)HH * HH));
        out[4] = (float)(g_acc[1] / ((double)HH * HH));
        out[5] = (float)(g_acc[5] / ((double)BB * HH));
    }
}

// ---------------------------------------------------------------------------
extern "C" void kernel_launch(void* const* d_in, const int* in_sizes, int n_in,
                              void* d_out, int out_size) {
    (void)in_sizes; (void)n_in; (void)out_size;
    const float* Xp  = (const float*)d_in[0];
    const float* Fe  = (const float*)d_in[1];
    const float* Fd  = (const float*)d_in[2];
    const float* Bsw = (const float*)d_in[3];
    const float* Mw  = (const float*)d_in[4];
    float* out = (float*)d_out;

    cudaFuncSetAttribute(k_zp_mma,     cudaFuncAttributeMaxDynamicSharedMemorySize, SMEM_MMA);
    cudaFuncSetAttribute(k_zt_f16,     cudaFuncAttributeMaxDynamicSharedMemorySize, SMEM_MMA);
    cudaFuncSetAttribute(k_recons_f16, cudaFuncAttributeMaxDynamicSharedMemorySize, SMEM_MMA);

    // Side stream + fork/join events (created fresh per call — kernel_launch
    // runs only for the correctness pass and the single capture pass, so the
    // leak is bounded; creation is a host API, legal during capture).
    cudaStream_t s2;
    cudaEvent_t evA, evB;
    cudaStreamCreateWithFlags(&s2, cudaStreamNonBlocking);
    cudaEventCreateWithFlags(&evA, cudaEventDisableTiming);
    cudaEventCreateWithFlags(&evB, cudaEventDisableTiming);

    // main: init, then fork convB (depends only on raw inputs + g_acc init)
    k_init<<<1, 32>>>();
    cudaEventRecord(evA, 0);
    cudaStreamWaitEvent(s2, evA, 0);
    k_convB<<<2048, 256, 0, s2>>>(Bsw, Mw);     // DRAM-bound, overlaps with zp
    cudaEventRecord(evB, s2);

    // main: conversions + tensor-bound GEMMs (disjoint bottleneck from convB)
    k_conv_x<<<(BB * DD + 255) / 256, 256>>>(Xp);
    k_conv_fe<<<dim3(DD / 32, HH / 32), dim3(32, 8)>>>(Fe);
    k_conv_fd<<<dim3(HH / 32, DD / 32), dim3(32, 8)>>>(Fd);
    k_zp_mma<<<dim3(HH / 128, BB / 128, TT), 256, SMEM_MMA>>>();
    k_recons_f16<<<dim3(DD / 128, BB / 128, 4), 256, SMEM_MMA>>>();
    k_sse<<<1024, 256>>>();

    // join: k_zt needs g_B16 (convB) and g_A16 (zp)
    cudaStreamWaitEvent(0, evB, 0);
    k_zt_f16<<<dim3(HH / 128, BB / 128, 4), 256, SMEM_MMA>>>();

    k_topk<<<BB, 256>>>();
    k_final<<<1, 32>>>(out);
}